// round 10
// baseline (speedup 1.0000x reference)
#include <cuda_runtime.h>
#include <cuda_fp16.h>
#include <math.h>
#include <stdint.h>

#define DIMM 768
#define HEADS 16
#define DH 48
#define NB 8
#define NSEQ 1024
#define ROWS 8192            // NB*NSEQ
#define QKVC 2304            // 3*DIMM
#define SLICE_SZ 49152       // NSEQ*DH
#define HEAD_BLK 786432      // HEADS*NSEQ*DH
#define THIRD 6291456        // NB*HEAD_BLK
#define ATT_SCALE 0.14433756729740643f  // 48^-0.5

// ---------------- scratch (__device__ globals; no allocation allowed) ------
__device__ __half g_qkvhi[ROWS * QKVC];      // qkv hi  (GEMM1 out)
__device__ __half g_qkvlo[ROWS * QKVC];      // qkv lo  (only Q third written)
__device__ __half g_xhi[ROWS * DIMM];
__device__ __half g_xlo[ROWS * DIMM];
__device__ __half g_chi[ROWS * DIMM];        // context hi (attn out)
__device__ __half g_clo[ROWS * DIMM];
__device__ __half g_wqh[QKVC * DIMM];        // Wqkv^T fp16 [2304,768]
__device__ __half g_woh[DIMM * DIMM];        // Wo^T fp16   [768,768]

// ---------------- PTX helpers (arch-agnostic: sm_80+ features only) --------
__device__ __forceinline__ uint32_t smem_u32(const void* p) {
    uint32_t a;
    asm("{ .reg .u64 t; cvta.to.shared.u64 t, %1; cvt.u32.u64 %0, t; }"
        : "=r"(a) : "l"(p));
    return a;
}
#define LDSM_X4(r0, r1, r2, r3, addr) \
    asm volatile("ldmatrix.sync.aligned.m8n8.x4.shared.b16 {%0,%1,%2,%3}, [%4];" \
                 : "=r"(r0), "=r"(r1), "=r"(r2), "=r"(r3) : "r"(addr))
#define LDSM_X2(r0, r1, addr) \
    asm volatile("ldmatrix.sync.aligned.m8n8.x2.shared.b16 {%0,%1}, [%2];" \
                 : "=r"(r0), "=r"(r1) : "r"(addr))
#define LDSM_X2T(r0, r1, addr) \
    asm volatile("ldmatrix.sync.aligned.m8n8.x2.trans.shared.b16 {%0,%1}, [%2];" \
                 : "=r"(r0), "=r"(r1) : "r"(addr))
#define MMA_F16(c, a, b) \
    asm volatile("mma.sync.aligned.m16n8k16.row.col.f32.f16.f16.f32 " \
                 "{%0,%1,%2,%3},{%4,%5,%6,%7},{%8,%9},{%0,%1,%2,%3};" \
                 : "+f"((c)[0]), "+f"((c)[1]), "+f"((c)[2]), "+f"((c)[3]) \
                 : "r"((a)[0]), "r"((a)[1]), "r"((a)[2]), "r"((a)[3]), \
                   "r"((b)[0]), "r"((b)[1]))
#define CP_ASYNC16(s, g) \
    asm volatile("cp.async.cg.shared.global [%0], [%1], 16;" :: "r"(s), "l"(g))
#define CP_COMMIT() asm volatile("cp.async.commit_group;" ::: "memory")
#define CP_WAIT1()  asm volatile("cp.async.wait_group 1;" ::: "memory")
#define CP_WAIT0()  asm volatile("cp.async.wait_group 0;" ::: "memory")

__device__ __forceinline__ uint32_t packh_hi(float a, float b, float& ra, float& rb) {
    __half2 t;
    t.x = __float2half_rn(a);
    t.y = __float2half_rn(b);
    ra = a - __half2float(t.x);
    rb = b - __half2float(t.y);
    return *(uint32_t*)&t;
}
__device__ __forceinline__ uint32_t packh2(float a, float b) {
    __half2 t;
    t.x = __float2half_rn(a);
    t.y = __float2half_rn(b);
    return *(uint32_t*)&t;
}

// ---------------------------------------------------------------------------
// fp16 one-sided-split GEMM on mma.sync: C = (Ahi+Alo) @ B^T (+bias).
// BM=BN=128, BK=64 (half the barriers vs BK=32), 8 warps,
// 3 tiles/stage (Ahi, Alo, B), 2-stage pipeline (110.6KB smem, 2 CTAs/SM).
// Row stride 144B: 128B payload + 16B pad; 144B = 36 words = 4 mod 32 banks
// -> ldmatrix 8-row reads hit disjoint bank quads (conflict-free).
// ---------------------------------------------------------------------------
#define BK 64
#define ROW_BYTES 144
#define TILE_BYTES (128 * ROW_BYTES)       // 18432
#define STAGE_BYTES (3 * TILE_BYTES)       // 55296 (Ahi, Alo, B)
#define NSTAGE 2
#define GEMM_SMEM (NSTAGE * STAGE_BYTES)   // 110592

__device__ __forceinline__ void stage_load(
    uint32_t sbyte, const __half* s0, const __half* s1, const __half* s2,
    int K, long kOff, int tid)
{
    const __half* srcs[3] = {s0, s1, s2};
    #pragma unroll
    for (int m = 0; m < 3; ++m) {
        #pragma unroll
        for (int t = 0; t < 4; ++t) {
            const int ch = tid * 4 + t;          // 0..1023 (128 rows x 8 chunks)
            const int row = ch >> 3;
            const int cc = ch & 7;
            const void* g = srcs[m] + (long)row * K + kOff + cc * 8;
            uint32_t s = sbyte + m * TILE_BYTES + row * ROW_BYTES + cc * 16;
            CP_ASYNC16(s, g);
        }
    }
}

__global__ __launch_bounds__(256, 2)
void mma_gemm(const __half* __restrict__ Ahi, const __half* __restrict__ Alo,
              const __half* __restrict__ B,
              const float* __restrict__ bias, float* __restrict__ C,
              __half* __restrict__ Ohi, __half* __restrict__ Olo,
              int loCols, int M, int Nc, int K)
{
    extern __shared__ char smem[];
    const uint32_t sb = smem_u32(smem);
    const int tid = threadIdx.x;
    const int wid = tid >> 5;
    const int lane = tid & 31;
    const int wr = wid >> 2;
    const int wc = wid & 3;
    const int rowBase = blockIdx.y << 7;
    const int colBase = blockIdx.x << 7;
    const int nch = K / BK;                  // 12 for K=768

    const __half* pAhi = Ahi + (long)rowBase * K;
    const __half* pAlo = Alo + (long)rowBase * K;
    const __half* pB   = B + (long)colBase * K;

    const int r8 = lane & 7;
    const int quad = lane >> 3;
    const int aRow = wr * 64 + (quad & 1) * 8 + r8;
    const int aColB = ((quad >> 1) * 8) * 2;
    const int bRow = wc * 32 + (lane & 7);
    const int bColB = (((lane >> 3) & 1) * 8) * 2;

    float acc[4][4][4];
    #pragma unroll
    for (int i = 0; i < 4; ++i)
        #pragma unroll
        for (int j = 0; j < 4; ++j)
            #pragma unroll
            for (int r = 0; r < 4; ++r) acc[i][j][r] = 0.f;

    // prologue: stage 0 in flight
    stage_load(sb, pAhi, pAlo, pB, K, 0, tid);
    CP_COMMIT();

    for (int c = 0; c < nch; ++c) {
        CP_WAIT0();        // this thread's stage-c copies retired
        __syncthreads();   // stage-c visible to all; compute c-1 done everywhere
        if (c + 1 < nch) { // other buffer freed by the barrier above
            stage_load(sb + ((c + 1) & 1) * STAGE_BYTES, pAhi, pAlo, pB,
                       K, (long)(c + 1) * BK, tid);
            CP_COMMIT();
        }

        const uint32_t stg = sb + (c & 1) * STAGE_BYTES;
        #pragma unroll
        for (int ks = 0; ks < 4; ++ks) {     // 4 x 16-col k-slices per chunk
            uint32_t ah[4][4], al[4][4];
            #pragma unroll
            for (int i = 0; i < 4; ++i) {
                uint32_t aoff = stg + (aRow + i * 16) * ROW_BYTES + aColB + ks * 32;
                LDSM_X4(ah[i][0], ah[i][1], ah[i][2], ah[i][3], aoff);
                LDSM_X4(al[i][0], al[i][1], al[i][2], al[i][3], aoff + TILE_BYTES);
            }
            uint32_t bfr[4][2];
            #pragma unroll
            for (int j = 0; j < 4; ++j) {
                uint32_t boff = stg + 2 * TILE_BYTES + (bRow + j * 8) * ROW_BYTES
                                + bColB + ks * 32;
                LDSM_X2(bfr[j][0], bfr[j][1], boff);
            }
            #pragma unroll
            for (int i = 0; i < 4; ++i)
                #pragma unroll
                for (int j = 0; j < 4; ++j)
                    MMA_F16(acc[i][j], ah[i], bfr[j]);
            #pragma unroll
            for (int i = 0; i < 4; ++i)
                #pragma unroll
                for (int j = 0; j < 4; ++j)
                    MMA_F16(acc[i][j], al[i], bfr[j]);
        }
    }

    #pragma unroll
    for (int i = 0; i < 4; ++i) {
        const long r0 = rowBase + wr * 64 + i * 16 + (lane >> 2);
        #pragma unroll
        for (int j = 0; j < 4; ++j) {
            const int col = wc * 32 + j * 8 + (lane & 3) * 2;
            if (Ohi != nullptr) {
                const bool wantLo = (colBase + col) < loCols;
                float ra, rb;
                uint32_t h0 = packh_hi(acc[i][j][0], acc[i][j][1], ra, rb);
                *(uint32_t*)(Ohi + r0 * Nc + colBase + col) = h0;
                if (wantLo)
                    *(uint32_t*)(Olo + r0 * Nc + colBase + col) = packh2(ra, rb);
                uint32_t h1 = packh_hi(acc[i][j][2], acc[i][j][3], ra, rb);
                *(uint32_t*)(Ohi + (r0 + 8) * Nc + colBase + col) = h1;
                if (wantLo)
                    *(uint32_t*)(Olo + (r0 + 8) * Nc + colBase + col) = packh2(ra, rb);
            } else {
                float b0 = 0.f, b1 = 0.f;
                if (bias != nullptr) {
                    b0 = bias[colBase + col];
                    b1 = bias[colBase + col + 1];
                }
                *(float2*)(C + r0 * Nc + colBase + col) =
                    make_float2(acc[i][j][0] + b0, acc[i][j][1] + b1);
                *(float2*)(C + (r0 + 8) * Nc + colBase + col) =
                    make_float2(acc[i][j][2] + b0, acc[i][j][3] + b1);
            }
        }
    }
}

// ---------------------------------------------------------------------------
// prep kernels
// ---------------------------------------------------------------------------
__global__ __launch_bounds__(256)
void split_kernel(const float* __restrict__ src, __half* __restrict__ hi,
                  __half* __restrict__ lo, int n)
{
    int i = blockIdx.x * 256 + threadIdx.x;
    if (i < n) {
        float v = src[i];
        __half h = __float2half_rn(v);
        hi[i] = h;
        lo[i] = __float2half_rn(v - __half2float(h));
    }
}

// W[K,Nc] -> W^T[Nc,K] single fp16
__global__ __launch_bounds__(256)
void tsingle_kernel(const float* __restrict__ W, __half* __restrict__ T,
                    int K, int Nc)
{
    __shared__ float t[32][33];
    const int n0 = blockIdx.x * 32;
    const int k0 = blockIdx.y * 32;
    const int lx = threadIdx.x & 31;
    const int ly = threadIdx.x >> 5;
    #pragma unroll
    for (int r = ly; r < 32; r += 8)
        t[r][lx] = W[(long)(k0 + r) * Nc + n0 + lx];
    __syncthreads();
    #pragma unroll
    for (int r = ly; r < 32; r += 8)
        T[(long)(n0 + r) * K + k0 + lx] = __float2half_rn(t[lx][r]);
}

// ---------------------------------------------------------------------------
// fp16 flash attention. CTA = 128 queries of one (b,h) slice. 8 warps.
// S = (Qhi+Qlo) K^T;  O += (Phi+Plo) V.  Keys 64/tile, 16 tiles,
// double-buffered with the corrected single-barrier schedule.
// ---------------------------------------------------------------------------
#define AT_STRIDE 112                       // bytes per smem row (48 fp16 + pad)
#define AT_Q_BYTES (128 * AT_STRIDE)        // 14336
#define AT_T_BYTES (64 * AT_STRIDE)         // 7168
#define AT_STAGE (2 * AT_T_BYTES)           // 14336 (Khi, Vhi)
#define ATT_SMEM (2 * AT_Q_BYTES + 2 * AT_STAGE)   // 57344

__device__ __forceinline__ void at_stage(
    uint32_t sdst, const __half* kh, const __half* vh, int key0, int tid)
{
    for (int i = tid; i < 384; i += 256) {
        const int r = i / 6, c = i % 6;
        const uint32_t off = r * AT_STRIDE + c * 16;
        const long gm = (long)(key0 + r) * DH + c * 8;
        CP_ASYNC16(sdst + off,              kh + gm);
        CP_ASYNC16(sdst + AT_T_BYTES + off, vh + gm);
    }
}

__global__ __launch_bounds__(256)
void attn_mma(const __half* __restrict__ qkvhi, const __half* __restrict__ qkvlo,
              __half* __restrict__ Chi, __half* __restrict__ Clo)
{
    extern __shared__ char smem[];
    const uint32_t sb = smem_u32(smem);
    const int tid = threadIdx.x;
    const int wid = tid >> 5;
    const int lane = tid & 31;
    const int slice = blockIdx.y;
    const int q0 = blockIdx.x << 7;

    const long base = (long)(slice >> 4) * HEAD_BLK + (long)(slice & 15) * SLICE_SZ;
    const __half* qh = qkvhi + base + (long)q0 * DH;
    const __half* ql = qkvlo + base + (long)q0 * DH;
    const __half* kh = qkvhi + THIRD + base;
    const __half* vh = qkvhi + 2L * THIRD + base;

    // group 0: Q tiles (hi+lo)
    for (int i = tid; i < 768; i += 256) {
        const int r = i / 6, c = i % 6;
        const uint32_t off = r * AT_STRIDE + c * 16;
        const long gm = (long)r * DH + c * 8;
        CP_ASYNC16(sb + off, qh + gm);
        CP_ASYNC16(sb + AT_Q_BYTES + off, ql + gm);
    }
    CP_COMMIT();
    // group 1: KV stage 0
    at_stage(sb + 2 * AT_Q_BYTES, kh, vh, 0, tid);
    CP_COMMIT();
    CP_WAIT1();          // Q retired (this thread)
    __syncthreads();     // Q visible to all

    // Q fragments (kept in regs for whole kernel)
    uint32_t qhf[3][4], qlf[3][4];
    {
        const int aRow = wid * 16 + ((lane >> 3) & 1) * 8 + (lane & 7);
        const int aColB = (lane >> 4) * 16;
        #pragma unroll
        for (int ks = 0; ks < 3; ++ks) {
            uint32_t addr = sb + aRow * AT_STRIDE + aColB + ks * 32;
            LDSM_X4(qhf[ks][0], qhf[ks][1], qhf[ks][2], qhf[ks][3], addr);
            LDSM_X4(qlf[ks][0], qlf[ks][1], qlf[ks][2], qlf[ks][3], addr + AT_Q_BYTES);
        }
    }

    float m1 = -INFINITY, m2 = -INFINITY, l1 = 0.f, l2 = 0.f;
    float o[6][4];
    #pragma unroll
    for (int n = 0; n < 6; ++n)
        #pragma unroll
        for (int r = 0; r < 4; ++r) o[n][r] = 0.f;

    const int kpair = lane >> 3;
    const int kRowOff = (kpair >> 1) * 8 + (lane & 7);
    const int kColB = (kpair & 1) * 16;
    const int vRowOff = (lane & 7) + ((lane >> 3) & 1) * 8;

    for (int kt = 0; kt < 16; ++kt) {
        CP_WAIT0();        // stage kt retired (this thread)
        __syncthreads();   // stage-kt visible; compute kt-1 done everywhere
        if (kt + 1 < 16) {
            at_stage(sb + 2 * AT_Q_BYTES + ((kt + 1) & 1) * AT_STAGE,
                     kh, vh, (kt + 1) * 64, tid);
            CP_COMMIT();
        }

        const uint32_t stg = sb + 2 * AT_Q_BYTES + (kt & 1) * AT_STAGE;

        // ---- S = (Qhi+Qlo) K^T ----
        float s[8][4];
        #pragma unroll
        for (int j = 0; j < 8; ++j)
            #pragma unroll
            for (int r = 0; r < 4; ++r) s[j][r] = 0.f;

        #pragma unroll
        for (int g = 0; g < 4; ++g) {
            #pragma unroll
            for (int ks = 0; ks < 3; ++ks) {
                const uint32_t ka = stg + (g * 16 + kRowOff) * AT_STRIDE
                                    + kColB + ks * 32;
                uint32_t kb[4];
                LDSM_X4(kb[0], kb[1], kb[2], kb[3], ka);
                MMA_F16(s[2 * g],     qhf[ks], kb);
                MMA_F16(s[2 * g + 1], qhf[ks], kb + 2);
                MMA_F16(s[2 * g],     qlf[ks], kb);
                MMA_F16(s[2 * g + 1], qlf[ks], kb + 2);
            }
        }

        // ---- online softmax ----
        #pragma unroll
        for (int j = 0; j < 8; ++j)
            #pragma unroll
            for (int r = 0; r < 4; ++r) s[j][r] *= ATT_SCALE;

        float mx1 = s[0][0], mx2 = s[0][2];
        #pragma unroll
        for (int j = 0; j < 8; ++j) {
            mx1 = fmaxf(mx1, fmaxf(s[j][0], s[j][1]));
            mx2 = fmaxf(mx2, fmaxf(s[j][2], s[j][3]));
        }
        mx1 = fmaxf(mx1, __shfl_xor_sync(0xffffffffu, mx1, 1));
        mx1 = fmaxf(mx1, __shfl_xor_sync(0xffffffffu, mx1, 2));
        mx2 = fmaxf(mx2, __shfl_xor_sync(0xffffffffu, mx2, 1));
        mx2 = fmaxf(mx2, __shfl_xor_sync(0xffffffffu, mx2, 2));

        const float nm1 = fmaxf(m1, mx1);
        const float nm2 = fmaxf(m2, mx2);
        const float e1 = __expf(m1 - nm1);
        const float e2 = __expf(m2 - nm2);
        m1 = nm1; m2 = nm2;

        float sum1 = 0.f, sum2 = 0.f;
        #pragma unroll
        for (int j = 0; j < 8; ++j) {
            s[j][0] = __expf(s[j][0] - m1);
            s[j][1] = __expf(s[j][1] - m1);
            s[j][2] = __expf(s[j][2] - m2);
            s[j][3] = __expf(s[j][3] - m2);
            sum1 += s[j][0] + s[j][1];
            sum2 += s[j][2] + s[j][3];
        }
        sum1 += __shfl_xor_sync(0xffffffffu, sum1, 1);
        sum1 += __shfl_xor_sync(0xffffffffu, sum1, 2);
        sum2 += __shfl_xor_sync(0xffffffffu, sum2, 1);
        sum2 += __shfl_xor_sync(0xffffffffu, sum2, 2);
        l1 = l1 * e1 + sum1;
        l2 = l2 * e2 + sum2;

        #pragma unroll
        for (int n = 0; n < 6; ++n) {
            o[n][0] *= e1; o[n][1] *= e1;
            o[n][2] *= e2; o[n][3] *= e2;
        }

        // ---- O += (Phi+Plo) V ----
        #pragma unroll
        for (int kk = 0; kk < 4; ++kk) {
            uint32_t ph[4], pl[4];
            float ra, rb;
            ph[0] = packh_hi(s[2 * kk][0], s[2 * kk][1], ra, rb);
            pl[0] = packh2(ra, rb);
            ph[1] = packh_hi(s[2 * kk][2], s[2 * kk][3], ra, rb);
            pl[1] = packh2(ra, rb);
            ph[2] = packh_hi(s[2 * kk + 1][0], s[2 * kk + 1][1], ra, rb);
            pl[2] = packh2(ra, rb);
            ph[3] = packh_hi(s[2 * kk + 1][2], s[2 * kk + 1][3], ra, rb);
            pl[3] = packh2(ra, rb);

            const uint32_t vrowA = stg + AT_T_BYTES
                                   + (kk * 16 + vRowOff) * AT_STRIDE;
            #pragma unroll
            for (int n = 0; n < 6; ++n) {
                uint32_t vb[2];
                LDSM_X2T(vb[0], vb[1], vrowA + n * 16);
                MMA_F16(o[n], ph, vb);
                MMA_F16(o[n], pl, vb);
            }
        }
    }

    // ---- epilogue: write context hi/lo at raw-reshape-flat offsets ----
    const float inv1 = 1.f / l1;
    const float inv2 = 1.f / l2;
    const long r1 = q0 + wid * 16 + (lane >> 2);
    const long r2 = r1 + 8;
    #pragma unroll
    for (int n = 0; n < 6; ++n) {
        const int col = n * 8 + (lane & 3) * 2;
        float ra, rb;
        uint32_t h0 = packh_hi(o[n][0] * inv1, o[n][1] * inv1, ra, rb);
        *(uint32_t*)(Chi + base + r1 * DH + col) = h0;
        *(uint32_t*)(Clo + base + r1 * DH + col) = packh2(ra, rb);
        uint32_t h1 = packh_hi(o[n][2] * inv2, o[n][3] * inv2, ra, rb);
        *(uint32_t*)(Chi + base + r2 * DH + col) = h1;
        *(uint32_t*)(Clo + base + r2 * DH + col) = packh2(ra, rb);
    }
}

// ---------------------------------------------------------------------------
extern "C" void kernel_launch(void* const* d_in, const int* in_sizes, int n_in,
                              void* d_out, int out_size)
{
    (void)in_sizes; (void)n_in; (void)out_size;
    const float* x    = (const float*)d_in[0];
    const float* Wqkv = (const float*)d_in[1];
    const float* Wo   = (const float*)d_in[2];
    const float* bo   = (const float*)d_in[3];
    float* out = (float*)d_out;

    void *qkvhi, *qkvlo, *xhi, *xlo, *chi, *clo, *wqh, *woh;
    cudaGetSymbolAddress(&qkvhi, g_qkvhi);
    cudaGetSymbolAddress(&qkvlo, g_qkvlo);
    cudaGetSymbolAddress(&xhi, g_xhi);
    cudaGetSymbolAddress(&xlo, g_xlo);
    cudaGetSymbolAddress(&chi, g_chi);
    cudaGetSymbolAddress(&clo, g_clo);
    cudaGetSymbolAddress(&wqh, g_wqh);
    cudaGetSymbolAddress(&woh, g_woh);

    cudaFuncSetAttribute(mma_gemm, cudaFuncAttributeMaxDynamicSharedMemorySize,
                         GEMM_SMEM);
    cudaFuncSetAttribute(attn_mma, cudaFuncAttributeMaxDynamicSharedMemorySize,
                         ATT_SMEM);

    // prep: split x (hi/lo fp16), transpose weights to single fp16
    split_kernel<<<(ROWS * DIMM + 255) / 256, 256>>>(
        x, (__half*)xhi, (__half*)xlo, ROWS * DIMM);
    tsingle_kernel<<<dim3(QKVC / 32, DIMM / 32), 256>>>(
        Wqkv, (__half*)wqh, DIMM, QKVC);
    tsingle_kernel<<<dim3(DIMM / 32, DIMM / 32), 256>>>(
        Wo, (__half*)woh, DIMM, DIMM);

    // 1) QKV projection -> fp16 hi (all) / lo (Q third only)
    mma_gemm<<<dim3(QKVC / 128, ROWS / 128), 256, GEMM_SMEM>>>(
        (const __half*)xhi, (const __half*)xlo, (const __half*)wqh,
        nullptr, nullptr,
        (__half*)qkvhi, (__half*)qkvlo, DIMM /*loCols: Q third*/,
        ROWS, QKVC, DIMM);

    // 2) fp16 flash attention -> context hi/lo
    attn_mma<<<dim3(NSEQ / 128, NB * HEADS), 256, ATT_SMEM>>>(
        (const __half*)qkvhi, (const __half*)qkvlo,
        (__half*)chi, (__half*)clo);

    // 3) output projection (+bias) -> fp32 out
    mma_gemm<<<dim3(DIMM / 128, ROWS / 128), 256, GEMM_SMEM>>>(
        (const __half*)chi, (const __half*)clo, (const __half*)woh,
        bo, out, nullptr, nullptr, 0,
        ROWS, DIMM, DIMM);
}

// round 11
// speedup vs baseline: 1.1102x; 1.1102x over previous
#include <cuda_runtime.h>
#include <cuda_fp16.h>
#include <math.h>
#include <stdint.h>

#define DIMM 768
#define HEADS 16
#define DH 48
#define NB 8
#define NSEQ 1024
#define ROWS 8192            // NB*NSEQ
#define QKVC 2304            // 3*DIMM
#define SLICE_SZ 49152       // NSEQ*DH
#define HEAD_BLK 786432      // HEADS*NSEQ*DH
#define THIRD 6291456        // NB*HEAD_BLK
// Q pre-scale: ATT_SCALE * log2(e) folded into Q fragments; softmax uses ex2.
#define QSCALE 0.20823030778170076f

// ---------------- scratch (__device__ globals; no allocation allowed) ------
__device__ __half g_qkvhi[ROWS * QKVC];      // qkv fp16 (GEMM1 out)
__device__ __half g_xhi[ROWS * DIMM];
__device__ __half g_xlo[ROWS * DIMM];
__device__ __half g_chi[ROWS * DIMM];        // context hi (attn out)
__device__ __half g_clo[ROWS * DIMM];
__device__ __half g_wqh[QKVC * DIMM];        // Wqkv^T fp16 [2304,768]
__device__ __half g_woh[DIMM * DIMM];        // Wo^T fp16   [768,768]

// ---------------- PTX helpers (arch-agnostic: sm_80+ features only) --------
__device__ __forceinline__ uint32_t smem_u32(const void* p) {
    uint32_t a;
    asm("{ .reg .u64 t; cvta.to.shared.u64 t, %1; cvt.u32.u64 %0, t; }"
        : "=r"(a) : "l"(p));
    return a;
}
__device__ __forceinline__ float ex2f(float x) {
    float r;
    asm("ex2.approx.ftz.f32 %0, %1;" : "=f"(r) : "f"(x));
    return r;
}
#define LDSM_X4(r0, r1, r2, r3, addr) \
    asm volatile("ldmatrix.sync.aligned.m8n8.x4.shared.b16 {%0,%1,%2,%3}, [%4];" \
                 : "=r"(r0), "=r"(r1), "=r"(r2), "=r"(r3) : "r"(addr))
#define LDSM_X2(r0, r1, addr) \
    asm volatile("ldmatrix.sync.aligned.m8n8.x2.shared.b16 {%0,%1}, [%2];" \
                 : "=r"(r0), "=r"(r1) : "r"(addr))
#define LDSM_X2T(r0, r1, addr) \
    asm volatile("ldmatrix.sync.aligned.m8n8.x2.trans.shared.b16 {%0,%1}, [%2];" \
                 : "=r"(r0), "=r"(r1) : "r"(addr))
#define MMA_F16(c, a, b) \
    asm volatile("mma.sync.aligned.m16n8k16.row.col.f32.f16.f16.f32 " \
                 "{%0,%1,%2,%3},{%4,%5,%6,%7},{%8,%9},{%0,%1,%2,%3};" \
                 : "+f"((c)[0]), "+f"((c)[1]), "+f"((c)[2]), "+f"((c)[3]) \
                 : "r"((a)[0]), "r"((a)[1]), "r"((a)[2]), "r"((a)[3]), \
                   "r"((b)[0]), "r"((b)[1]))
#define CP_ASYNC16(s, g) \
    asm volatile("cp.async.cg.shared.global [%0], [%1], 16;" :: "r"(s), "l"(g))
#define CP_COMMIT() asm volatile("cp.async.commit_group;" ::: "memory")
#define CP_WAIT1()  asm volatile("cp.async.wait_group 1;" ::: "memory")
#define CP_WAIT0()  asm volatile("cp.async.wait_group 0;" ::: "memory")

__device__ __forceinline__ uint32_t packh_hi(float a, float b, float& ra, float& rb) {
    __half2 t;
    t.x = __float2half_rn(a);
    t.y = __float2half_rn(b);
    ra = a - __half2float(t.x);
    rb = b - __half2float(t.y);
    return *(uint32_t*)&t;
}
__device__ __forceinline__ uint32_t packh2(float a, float b) {
    __half2 t;
    t.x = __float2half_rn(a);
    t.y = __float2half_rn(b);
    return *(uint32_t*)&t;
}

// ---------------------------------------------------------------------------
// fp16 one-sided-split GEMM on mma.sync: C = (Ahi+Alo) @ B^T (+bias).
// BM=BN=128, BK=32, 8 warps, 3 tiles/stage (Ahi, Alo, B), 3-stage pipeline.
// (R8 measured-best config: 207us, tensor 46%.)
// ---------------------------------------------------------------------------
#define BK 32
#define ROW_BYTES 80
#define TILE_BYTES (128 * ROW_BYTES)       // 10240
#define STAGE_BYTES (3 * TILE_BYTES)       // 30720 (Ahi, Alo, B)
#define NSTAGE 3
#define GEMM_SMEM (NSTAGE * STAGE_BYTES)   // 92160

__device__ __forceinline__ void stage_load(
    uint32_t sbyte, const __half* s0, const __half* s1, const __half* s2,
    int K, long kOff, int tid)
{
    const __half* srcs[3] = {s0, s1, s2};
    #pragma unroll
    for (int m = 0; m < 3; ++m) {
        #pragma unroll
        for (int t = 0; t < 2; ++t) {
            const int ch = tid * 2 + t;          // 0..511
            const int row = ch >> 2;
            const int cc = ch & 3;
            const void* g = srcs[m] + (long)row * K + kOff + cc * 8;
            uint32_t s = sbyte + m * TILE_BYTES + row * ROW_BYTES + cc * 16;
            CP_ASYNC16(s, g);
        }
    }
}

__global__ __launch_bounds__(256, 2)
void mma_gemm(const __half* __restrict__ Ahi, const __half* __restrict__ Alo,
              const __half* __restrict__ B,
              const float* __restrict__ bias, float* __restrict__ C,
              __half* __restrict__ Ohi,
              int M, int Nc, int K)
{
    extern __shared__ char smem[];
    const uint32_t sb = smem_u32(smem);
    const int tid = threadIdx.x;
    const int wid = tid >> 5;
    const int lane = tid & 31;
    const int wr = wid >> 2;
    const int wc = wid & 3;
    const int rowBase = blockIdx.y << 7;
    const int colBase = blockIdx.x << 7;
    const int nch = K / BK;

    const __half* pAhi = Ahi + (long)rowBase * K;
    const __half* pAlo = Alo + (long)rowBase * K;
    const __half* pB   = B + (long)colBase * K;

    const int r8 = lane & 7;
    const int quad = lane >> 3;
    const int aRow = wr * 64 + (quad & 1) * 8 + r8;
    const int aColB = ((quad >> 1) * 8) * 2;
    const int bRow = wc * 32 + (lane & 7);
    const int bColB = (((lane >> 3) & 1) * 8) * 2;

    float acc[4][4][4];
    #pragma unroll
    for (int i = 0; i < 4; ++i)
        #pragma unroll
        for (int j = 0; j < 4; ++j)
            #pragma unroll
            for (int r = 0; r < 4; ++r) acc[i][j][r] = 0.f;

    // prologue: stages 0, 1 in flight
    stage_load(sb, pAhi, pAlo, pB, K, 0, tid);
    CP_COMMIT();
    stage_load(sb + STAGE_BYTES, pAhi, pAlo, pB, K, BK, tid);
    CP_COMMIT();

    for (int c = 0; c < nch; ++c) {
        if (c + 1 < nch) { CP_WAIT1(); } else { CP_WAIT0(); }  // stage c retired
        __syncthreads();   // stage-c visible to all; compute c-1 done everywhere
        if (c + 2 < nch) { // slot (c+2)%NSTAGE freed (last read at compute c-1)
            stage_load(sb + ((c + 2) % NSTAGE) * STAGE_BYTES, pAhi, pAlo, pB,
                       K, (long)(c + 2) * BK, tid);
            CP_COMMIT();
        }

        const uint32_t stg = sb + (c % NSTAGE) * STAGE_BYTES;
        #pragma unroll
        for (int ks = 0; ks < 2; ++ks) {
            uint32_t ah[4][4], al[4][4];
            #pragma unroll
            for (int i = 0; i < 4; ++i) {
                uint32_t aoff = stg + (aRow + i * 16) * ROW_BYTES + aColB + ks * 32;
                LDSM_X4(ah[i][0], ah[i][1], ah[i][2], ah[i][3], aoff);
                LDSM_X4(al[i][0], al[i][1], al[i][2], al[i][3], aoff + TILE_BYTES);
            }
            uint32_t bfr[4][2];
            #pragma unroll
            for (int j = 0; j < 4; ++j) {
                uint32_t boff = stg + 2 * TILE_BYTES + (bRow + j * 8) * ROW_BYTES
                                + bColB + ks * 32;
                LDSM_X2(bfr[j][0], bfr[j][1], boff);
            }
            #pragma unroll
            for (int i = 0; i < 4; ++i)
                #pragma unroll
                for (int j = 0; j < 4; ++j)
                    MMA_F16(acc[i][j], ah[i], bfr[j]);
            #pragma unroll
            for (int i = 0; i < 4; ++i)
                #pragma unroll
                for (int j = 0; j < 4; ++j)
                    MMA_F16(acc[i][j], al[i], bfr[j]);
        }
    }

    #pragma unroll
    for (int i = 0; i < 4; ++i) {
        const long r0 = rowBase + wr * 64 + i * 16 + (lane >> 2);
        #pragma unroll
        for (int j = 0; j < 4; ++j) {
            const int col = wc * 32 + j * 8 + (lane & 3) * 2;
            if (Ohi != nullptr) {
                *(uint32_t*)(Ohi + r0 * Nc + colBase + col) =
                    packh2(acc[i][j][0], acc[i][j][1]);
                *(uint32_t*)(Ohi + (r0 + 8) * Nc + colBase + col) =
                    packh2(acc[i][j][2], acc[i][j][3]);
            } else {
                float b0 = 0.f, b1 = 0.f;
                if (bias != nullptr) {
                    b0 = bias[colBase + col];
                    b1 = bias[colBase + col + 1];
                }
                *(float2*)(C + r0 * Nc + colBase + col) =
                    make_float2(acc[i][j][0] + b0, acc[i][j][1] + b1);
                *(float2*)(C + (r0 + 8) * Nc + colBase + col) =
                    make_float2(acc[i][j][2] + b0, acc[i][j][3] + b1);
            }
        }
    }
}

// ---------------------------------------------------------------------------
// prep kernels
// ---------------------------------------------------------------------------
__global__ __launch_bounds__(256)
void split_kernel(const float* __restrict__ src, __half* __restrict__ hi,
                  __half* __restrict__ lo, int n)
{
    int i = blockIdx.x * 256 + threadIdx.x;
    if (i < n) {
        float v = src[i];
        __half h = __float2half_rn(v);
        hi[i] = h;
        lo[i] = __float2half_rn(v - __half2float(h));
    }
}

// W[K,Nc] -> W^T[Nc,K] single fp16
__global__ __launch_bounds__(256)
void tsingle_kernel(const float* __restrict__ W, __half* __restrict__ T,
                    int K, int Nc)
{
    __shared__ float t[32][33];
    const int n0 = blockIdx.x * 32;
    const int k0 = blockIdx.y * 32;
    const int lx = threadIdx.x & 31;
    const int ly = threadIdx.x >> 5;
    #pragma unroll
    for (int r = ly; r < 32; r += 8)
        t[r][lx] = W[(long)(k0 + r) * Nc + n0 + lx];
    __syncthreads();
    #pragma unroll
    for (int r = ly; r < 32; r += 8)
        T[(long)(n0 + r) * K + k0 + lx] = __float2half_rn(t[lx][r]);
}

// ---------------------------------------------------------------------------
// fp16 flash attention. CTA = 128 queries of one (b,h) slice. 8 warps.
// S = Q K^T (single pass; Q pre-scaled by ATT_SCALE*log2e at fragment load,
// softmax in exp2 domain). O += (Phi+Plo) V.
// Keys 64/tile, 16 tiles, double-buffered single-barrier schedule.
// ---------------------------------------------------------------------------
#define AT_STRIDE 112                       // bytes per smem row (48 fp16 + pad)
#define AT_Q_BYTES (128 * AT_STRIDE)        // 14336
#define AT_T_BYTES (64 * AT_STRIDE)         // 7168
#define AT_STAGE (2 * AT_T_BYTES)           // 14336 (K, V)
#define ATT_SMEM (AT_Q_BYTES + 2 * AT_STAGE)   // 43008

__device__ __forceinline__ void at_stage(
    uint32_t sdst, const __half* kh, const __half* vh, int key0, int tid)
{
    for (int i = tid; i < 384; i += 256) {
        const int r = i / 6, c = i % 6;
        const uint32_t off = r * AT_STRIDE + c * 16;
        const long gm = (long)(key0 + r) * DH + c * 8;
        CP_ASYNC16(sdst + off,              kh + gm);
        CP_ASYNC16(sdst + AT_T_BYTES + off, vh + gm);
    }
}

__global__ __launch_bounds__(256)
void attn_mma(const __half* __restrict__ qkvhi,
              __half* __restrict__ Chi, __half* __restrict__ Clo)
{
    extern __shared__ char smem[];
    const uint32_t sb = smem_u32(smem);
    const int tid = threadIdx.x;
    const int wid = tid >> 5;
    const int lane = tid & 31;
    const int slice = blockIdx.y;
    const int q0 = blockIdx.x << 7;

    const long base = (long)(slice >> 4) * HEAD_BLK + (long)(slice & 15) * SLICE_SZ;
    const __half* qh = qkvhi + base + (long)q0 * DH;
    const __half* kh = qkvhi + THIRD + base;
    const __half* vh = qkvhi + 2L * THIRD + base;

    // group 0: Q tile
    for (int i = tid; i < 768; i += 256) {
        const int r = i / 6, c = i % 6;
        CP_ASYNC16(sb + r * AT_STRIDE + c * 16, qh + (long)r * DH + c * 8);
    }
    CP_COMMIT();
    // group 1: KV stage 0
    at_stage(sb + AT_Q_BYTES, kh, vh, 0, tid);
    CP_COMMIT();
    CP_WAIT1();          // Q retired (this thread)
    __syncthreads();     // Q visible to all

    // Q fragments (kept in regs, pre-scaled by ATT_SCALE*log2e)
    uint32_t qhf[3][4];
    {
        const int aRow = wid * 16 + ((lane >> 3) & 1) * 8 + (lane & 7);
        const int aColB = (lane >> 4) * 16;
        const __half2 qs = __float2half2_rn(QSCALE);
        #pragma unroll
        for (int ks = 0; ks < 3; ++ks) {
            uint32_t addr = sb + aRow * AT_STRIDE + aColB + ks * 32;
            LDSM_X4(qhf[ks][0], qhf[ks][1], qhf[ks][2], qhf[ks][3], addr);
            #pragma unroll
            for (int r = 0; r < 4; ++r) {
                __half2 v = *(__half2*)&qhf[ks][r];
                v = __hmul2(v, qs);
                qhf[ks][r] = *(uint32_t*)&v;
            }
        }
    }

    float m1 = -INFINITY, m2 = -INFINITY, l1 = 0.f, l2 = 0.f;
    float o[6][4];
    #pragma unroll
    for (int n = 0; n < 6; ++n)
        #pragma unroll
        for (int r = 0; r < 4; ++r) o[n][r] = 0.f;

    const int kpair = lane >> 3;
    const int kRowOff = (kpair >> 1) * 8 + (lane & 7);
    const int kColB = (kpair & 1) * 16;
    const int vRowOff = (lane & 7) + ((lane >> 3) & 1) * 8;

    for (int kt = 0; kt < 16; ++kt) {
        CP_WAIT0();        // stage kt retired (this thread)
        __syncthreads();   // stage-kt visible; compute kt-1 done everywhere
        if (kt + 1 < 16) {
            at_stage(sb + AT_Q_BYTES + ((kt + 1) & 1) * AT_STAGE,
                     kh, vh, (kt + 1) * 64, tid);
            CP_COMMIT();
        }

        const uint32_t stg = sb + AT_Q_BYTES + (kt & 1) * AT_STAGE;

        // ---- S = Q K^T (pre-scaled; log2 domain) ----
        float s[8][4];
        #pragma unroll
        for (int j = 0; j < 8; ++j)
            #pragma unroll
            for (int r = 0; r < 4; ++r) s[j][r] = 0.f;

        #pragma unroll
        for (int g = 0; g < 4; ++g) {
            #pragma unroll
            for (int ks = 0; ks < 3; ++ks) {
                const uint32_t ka = stg + (g * 16 + kRowOff) * AT_STRIDE
                                    + kColB + ks * 32;
                uint32_t kb[4];
                LDSM_X4(kb[0], kb[1], kb[2], kb[3], ka);
                MMA_F16(s[2 * g],     qhf[ks], kb);
                MMA_F16(s[2 * g + 1], qhf[ks], kb + 2);
            }
        }

        // ---- online softmax (exp2 domain) ----
        float mx1 = s[0][0], mx2 = s[0][2];
        #pragma unroll
        for (int j = 0; j < 8; ++j) {
            mx1 = fmaxf(mx1, fmaxf(s[j][0], s[j][1]));
            mx2 = fmaxf(mx2, fmaxf(s[j][2], s[j][3]));
        }
        mx1 = fmaxf(mx1, __shfl_xor_sync(0xffffffffu, mx1, 1));
        mx1 = fmaxf(mx1, __shfl_xor_sync(0xffffffffu, mx1, 2));
        mx2 = fmaxf(mx2, __shfl_xor_sync(0xffffffffu, mx2, 1));
        mx2 = fmaxf(mx2, __shfl_xor_sync(0xffffffffu, mx2, 2));

        const float nm1 = fmaxf(m1, mx1);
        const float nm2 = fmaxf(m2, mx2);
        const float e1 = ex2f(m1 - nm1);
        const float e2 = ex2f(m2 - nm2);
        m1 = nm1; m2 = nm2;

        float sum1 = 0.f, sum2 = 0.f;
        #pragma unroll
        for (int j = 0; j < 8; ++j) {
            s[j][0] = ex2f(s[j][0] - m1);
            s[j][1] = ex2f(s[j][1] - m1);
            s[j][2] = ex2f(s[j][2] - m2);
            s[j][3] = ex2f(s[j][3] - m2);
            sum1 += s[j][0] + s[j][1];
            sum2 += s[j][2] + s[j][3];
        }
        sum1 += __shfl_xor_sync(0xffffffffu, sum1, 1);
        sum1 += __shfl_xor_sync(0xffffffffu, sum1, 2);
        sum2 += __shfl_xor_sync(0xffffffffu, sum2, 1);
        sum2 += __shfl_xor_sync(0xffffffffu, sum2, 2);
        l1 = l1 * e1 + sum1;
        l2 = l2 * e2 + sum2;

        #pragma unroll
        for (int n = 0; n < 6; ++n) {
            o[n][0] *= e1; o[n][1] *= e1;
            o[n][2] *= e2; o[n][3] *= e2;
        }

        // ---- O += (Phi+Plo) V ----
        #pragma unroll
        for (int kk = 0; kk < 4; ++kk) {
            uint32_t ph[4], pl[4];
            float ra, rb;
            ph[0] = packh_hi(s[2 * kk][0], s[2 * kk][1], ra, rb);
            pl[0] = packh2(ra, rb);
            ph[1] = packh_hi(s[2 * kk][2], s[2 * kk][3], ra, rb);
            pl[1] = packh2(ra, rb);
            ph[2] = packh_hi(s[2 * kk + 1][0], s[2 * kk + 1][1], ra, rb);
            pl[2] = packh2(ra, rb);
            ph[3] = packh_hi(s[2 * kk + 1][2], s[2 * kk + 1][3], ra, rb);
            pl[3] = packh2(ra, rb);

            const uint32_t vrowA = stg + AT_T_BYTES
                                   + (kk * 16 + vRowOff) * AT_STRIDE;
            #pragma unroll
            for (int n = 0; n < 6; ++n) {
                uint32_t vb[2];
                LDSM_X2T(vb[0], vb[1], vrowA + n * 16);
                MMA_F16(o[n], ph, vb);
                MMA_F16(o[n], pl, vb);
            }
        }
    }

    // ---- epilogue: write context hi/lo at raw-reshape-flat offsets ----
    const float inv1 = 1.f / l1;
    const float inv2 = 1.f / l2;
    const long r1 = q0 + wid * 16 + (lane >> 2);
    const long r2 = r1 + 8;
    #pragma unroll
    for (int n = 0; n < 6; ++n) {
        const int col = n * 8 + (lane & 3) * 2;
        float ra, rb;
        uint32_t h0 = packh_hi(o[n][0] * inv1, o[n][1] * inv1, ra, rb);
        *(uint32_t*)(Chi + base + r1 * DH + col) = h0;
        *(uint32_t*)(Clo + base + r1 * DH + col) = packh2(ra, rb);
        uint32_t h1 = packh_hi(o[n][2] * inv2, o[n][3] * inv2, ra, rb);
        *(uint32_t*)(Chi + base + r2 * DH + col) = h1;
        *(uint32_t*)(Clo + base + r2 * DH + col) = packh2(ra, rb);
    }
}

// ---------------------------------------------------------------------------
extern "C" void kernel_launch(void* const* d_in, const int* in_sizes, int n_in,
                              void* d_out, int out_size)
{
    (void)in_sizes; (void)n_in; (void)out_size;
    const float* x    = (const float*)d_in[0];
    const float* Wqkv = (const float*)d_in[1];
    const float* Wo   = (const float*)d_in[2];
    const float* bo   = (const float*)d_in[3];
    float* out = (float*)d_out;

    void *qkvhi, *xhi, *xlo, *chi, *clo, *wqh, *woh;
    cudaGetSymbolAddress(&qkvhi, g_qkvhi);
    cudaGetSymbolAddress(&xhi, g_xhi);
    cudaGetSymbolAddress(&xlo, g_xlo);
    cudaGetSymbolAddress(&chi, g_chi);
    cudaGetSymbolAddress(&clo, g_clo);
    cudaGetSymbolAddress(&wqh, g_wqh);
    cudaGetSymbolAddress(&woh, g_woh);

    cudaFuncSetAttribute(mma_gemm, cudaFuncAttributeMaxDynamicSharedMemorySize,
                         GEMM_SMEM);
    cudaFuncSetAttribute(attn_mma, cudaFuncAttributeMaxDynamicSharedMemorySize,
                         ATT_SMEM);

    // prep: split x (hi/lo fp16), transpose weights to single fp16
    split_kernel<<<(ROWS * DIMM + 255) / 256, 256>>>(
        x, (__half*)xhi, (__half*)xlo, ROWS * DIMM);
    tsingle_kernel<<<dim3(QKVC / 32, DIMM / 32), 256>>>(
        Wqkv, (__half*)wqh, DIMM, QKVC);
    tsingle_kernel<<<dim3(DIMM / 32, DIMM / 32), 256>>>(
        Wo, (__half*)woh, DIMM, DIMM);

    // 1) QKV projection -> fp16 qkv
    mma_gemm<<<dim3(QKVC / 128, ROWS / 128), 256, GEMM_SMEM>>>(
        (const __half*)xhi, (const __half*)xlo, (const __half*)wqh,
        nullptr, nullptr, (__half*)qkvhi,
        ROWS, QKVC, DIMM);

    // 2) fp16 flash attention -> context hi/lo
    attn_mma<<<dim3(NSEQ / 128, NB * HEADS), 256, ATT_SMEM>>>(
        (const __half*)qkvhi, (__half*)chi, (__half*)clo);

    // 3) output projection (+bias) -> fp32 out
    mma_gemm<<<dim3(DIMM / 128, ROWS / 128), 256, GEMM_SMEM>>>(
        (const __half*)chi, (const __half*)clo, (const __half*)woh,
        bo, out, nullptr,
        ROWS, DIMM, DIMM);
}

// round 12
// speedup vs baseline: 1.2011x; 1.0819x over previous
#include <cuda_runtime.h>
#include <cuda_fp16.h>
#include <math.h>
#include <stdint.h>

#define DIMM 768
#define HEADS 16
#define DH 48
#define NB 8
#define NSEQ 1024
#define ROWS 8192            // NB*NSEQ
#define QKVC 2304            // 3*DIMM
#define SLICE_SZ 49152       // NSEQ*DH
#define HEAD_BLK 786432      // HEADS*NSEQ*DH
#define THIRD 6291456        // NB*HEAD_BLK
// Q pre-scale: ATT_SCALE * log2(e) folded into Q fragments; softmax uses ex2.
#define QSCALE 0.20823030778170076f

// ---------------- scratch (__device__ globals; no allocation allowed) ------
__device__ __half g_qkvhi[ROWS * QKVC];      // qkv fp16 (GEMM1 out)
__device__ __half g_xhi[ROWS * DIMM];
__device__ __half g_xlo[ROWS * DIMM];
__device__ __half g_chi[ROWS * DIMM];        // context hi (attn out)
__device__ __half g_clo[ROWS * DIMM];
__device__ __half g_wqh[QKVC * DIMM];        // Wqkv^T fp16 [2304,768]
__device__ __half g_woh[DIMM * DIMM];        // Wo^T fp16   [768,768]

// ---------------- PTX helpers (arch-agnostic: sm_80+ features only) --------
__device__ __forceinline__ uint32_t smem_u32(const void* p) {
    uint32_t a;
    asm("{ .reg .u64 t; cvta.to.shared.u64 t, %1; cvt.u32.u64 %0, t; }"
        : "=r"(a) : "l"(p));
    return a;
}
__device__ __forceinline__ float ex2f(float x) {
    float r;
    asm("ex2.approx.ftz.f32 %0, %1;" : "=f"(r) : "f"(x));
    return r;
}
#define LDSM_X4(r0, r1, r2, r3, addr) \
    asm volatile("ldmatrix.sync.aligned.m8n8.x4.shared.b16 {%0,%1,%2,%3}, [%4];" \
                 : "=r"(r0), "=r"(r1), "=r"(r2), "=r"(r3) : "r"(addr))
#define LDSM_X2(r0, r1, addr) \
    asm volatile("ldmatrix.sync.aligned.m8n8.x2.shared.b16 {%0,%1}, [%2];" \
                 : "=r"(r0), "=r"(r1) : "r"(addr))
#define LDSM_X2T(r0, r1, addr) \
    asm volatile("ldmatrix.sync.aligned.m8n8.x2.trans.shared.b16 {%0,%1}, [%2];" \
                 : "=r"(r0), "=r"(r1) : "r"(addr))
#define MMA_F16(c, a, b) \
    asm volatile("mma.sync.aligned.m16n8k16.row.col.f32.f16.f16.f32 " \
                 "{%0,%1,%2,%3},{%4,%5,%6,%7},{%8,%9},{%0,%1,%2,%3};" \
                 : "+f"((c)[0]), "+f"((c)[1]), "+f"((c)[2]), "+f"((c)[3]) \
                 : "r"((a)[0]), "r"((a)[1]), "r"((a)[2]), "r"((a)[3]), \
                   "r"((b)[0]), "r"((b)[1]))
#define CP_ASYNC16(s, g) \
    asm volatile("cp.async.cg.shared.global [%0], [%1], 16;" :: "r"(s), "l"(g))
#define CP_COMMIT() asm volatile("cp.async.commit_group;" ::: "memory")
#define CP_WAIT1()  asm volatile("cp.async.wait_group 1;" ::: "memory")
#define CP_WAIT0()  asm volatile("cp.async.wait_group 0;" ::: "memory")

__device__ __forceinline__ uint32_t packh_hi(float a, float b, float& ra, float& rb) {
    __half2 t;
    t.x = __float2half_rn(a);
    t.y = __float2half_rn(b);
    ra = a - __half2float(t.x);
    rb = b - __half2float(t.y);
    return *(uint32_t*)&t;
}
__device__ __forceinline__ uint32_t packh2(float a, float b) {
    __half2 t;
    t.x = __float2half_rn(a);
    t.y = __float2half_rn(b);
    return *(uint32_t*)&t;
}

// ---------------------------------------------------------------------------
// fp16 one-sided-split GEMM on mma.sync: C = (Ahi+Alo) @ B^T (+bias).
// BM=BN=128, BK=32, 8 warps, 3 tiles/stage (Ahi, Alo, B), 3-stage pipeline.
// (R8/R10 measured-best config.)
// ---------------------------------------------------------------------------
#define BK 32
#define ROW_BYTES 80
#define TILE_BYTES (128 * ROW_BYTES)       // 10240
#define STAGE_BYTES (3 * TILE_BYTES)       // 30720 (Ahi, Alo, B)
#define NSTAGE 3
#define GEMM_SMEM (NSTAGE * STAGE_BYTES)   // 92160

__device__ __forceinline__ void stage_load(
    uint32_t sbyte, const __half* s0, const __half* s1, const __half* s2,
    int K, long kOff, int tid)
{
    const __half* srcs[3] = {s0, s1, s2};
    #pragma unroll
    for (int m = 0; m < 3; ++m) {
        #pragma unroll
        for (int t = 0; t < 2; ++t) {
            const int ch = tid * 2 + t;          // 0..511
            const int row = ch >> 2;
            const int cc = ch & 3;
            const void* g = srcs[m] + (long)row * K + kOff + cc * 8;
            uint32_t s = sbyte + m * TILE_BYTES + row * ROW_BYTES + cc * 16;
            CP_ASYNC16(s, g);
        }
    }
}

__global__ __launch_bounds__(256, 2)
void mma_gemm(const __half* __restrict__ Ahi, const __half* __restrict__ Alo,
              const __half* __restrict__ B,
              const float* __restrict__ bias, float* __restrict__ C,
              __half* __restrict__ Ohi,
              int M, int Nc, int K)
{
    extern __shared__ char smem[];
    const uint32_t sb = smem_u32(smem);
    const int tid = threadIdx.x;
    const int wid = tid >> 5;
    const int lane = tid & 31;
    const int wr = wid >> 2;
    const int wc = wid & 3;
    const int rowBase = blockIdx.y << 7;
    const int colBase = blockIdx.x << 7;
    const int nch = K / BK;

    const __half* pAhi = Ahi + (long)rowBase * K;
    const __half* pAlo = Alo + (long)rowBase * K;
    const __half* pB   = B + (long)colBase * K;

    const int r8 = lane & 7;
    const int quad = lane >> 3;
    const int aRow = wr * 64 + (quad & 1) * 8 + r8;
    const int aColB = ((quad >> 1) * 8) * 2;
    const int bRow = wc * 32 + (lane & 7);
    const int bColB = (((lane >> 3) & 1) * 8) * 2;

    float acc[4][4][4];
    #pragma unroll
    for (int i = 0; i < 4; ++i)
        #pragma unroll
        for (int j = 0; j < 4; ++j)
            #pragma unroll
            for (int r = 0; r < 4; ++r) acc[i][j][r] = 0.f;

    // prologue: stages 0, 1 in flight
    stage_load(sb, pAhi, pAlo, pB, K, 0, tid);
    CP_COMMIT();
    stage_load(sb + STAGE_BYTES, pAhi, pAlo, pB, K, BK, tid);
    CP_COMMIT();

    for (int c = 0; c < nch; ++c) {
        if (c + 1 < nch) { CP_WAIT1(); } else { CP_WAIT0(); }  // stage c retired
        __syncthreads();   // stage-c visible to all; compute c-1 done everywhere
        if (c + 2 < nch) { // slot (c+2)%NSTAGE freed (last read at compute c-1)
            stage_load(sb + ((c + 2) % NSTAGE) * STAGE_BYTES, pAhi, pAlo, pB,
                       K, (long)(c + 2) * BK, tid);
            CP_COMMIT();
        }

        const uint32_t stg = sb + (c % NSTAGE) * STAGE_BYTES;
        #pragma unroll
        for (int ks = 0; ks < 2; ++ks) {
            uint32_t ah[4][4], al[4][4];
            #pragma unroll
            for (int i = 0; i < 4; ++i) {
                uint32_t aoff = stg + (aRow + i * 16) * ROW_BYTES + aColB + ks * 32;
                LDSM_X4(ah[i][0], ah[i][1], ah[i][2], ah[i][3], aoff);
                LDSM_X4(al[i][0], al[i][1], al[i][2], al[i][3], aoff + TILE_BYTES);
            }
            uint32_t bfr[4][2];
            #pragma unroll
            for (int j = 0; j < 4; ++j) {
                uint32_t boff = stg + 2 * TILE_BYTES + (bRow + j * 8) * ROW_BYTES
                                + bColB + ks * 32;
                LDSM_X2(bfr[j][0], bfr[j][1], boff);
            }
            #pragma unroll
            for (int i = 0; i < 4; ++i)
                #pragma unroll
                for (int j = 0; j < 4; ++j)
                    MMA_F16(acc[i][j], ah[i], bfr[j]);
            #pragma unroll
            for (int i = 0; i < 4; ++i)
                #pragma unroll
                for (int j = 0; j < 4; ++j)
                    MMA_F16(acc[i][j], al[i], bfr[j]);
        }
    }

    #pragma unroll
    for (int i = 0; i < 4; ++i) {
        const long r0 = rowBase + wr * 64 + i * 16 + (lane >> 2);
        #pragma unroll
        for (int j = 0; j < 4; ++j) {
            const int col = wc * 32 + j * 8 + (lane & 3) * 2;
            if (Ohi != nullptr) {
                *(uint32_t*)(Ohi + r0 * Nc + colBase + col) =
                    packh2(acc[i][j][0], acc[i][j][1]);
                *(uint32_t*)(Ohi + (r0 + 8) * Nc + colBase + col) =
                    packh2(acc[i][j][2], acc[i][j][3]);
            } else {
                float b0 = 0.f, b1 = 0.f;
                if (bias != nullptr) {
                    b0 = bias[colBase + col];
                    b1 = bias[colBase + col + 1];
                }
                *(float2*)(C + r0 * Nc + colBase + col) =
                    make_float2(acc[i][j][0] + b0, acc[i][j][1] + b1);
                *(float2*)(C + (r0 + 8) * Nc + colBase + col) =
                    make_float2(acc[i][j][2] + b0, acc[i][j][3] + b1);
            }
        }
    }
}

// ---------------------------------------------------------------------------
// prep kernels
// ---------------------------------------------------------------------------
__global__ __launch_bounds__(256)
void split_kernel(const float* __restrict__ src, __half* __restrict__ hi,
                  __half* __restrict__ lo, int n)
{
    int i = blockIdx.x * 256 + threadIdx.x;
    if (i < n) {
        float v = src[i];
        __half h = __float2half_rn(v);
        hi[i] = h;
        lo[i] = __float2half_rn(v - __half2float(h));
    }
}

// W[K,Nc] -> W^T[Nc,K] single fp16
__global__ __launch_bounds__(256)
void tsingle_kernel(const float* __restrict__ W, __half* __restrict__ T,
                    int K, int Nc)
{
    __shared__ float t[32][33];
    const int n0 = blockIdx.x * 32;
    const int k0 = blockIdx.y * 32;
    const int lx = threadIdx.x & 31;
    const int ly = threadIdx.x >> 5;
    #pragma unroll
    for (int r = ly; r < 32; r += 8)
        t[r][lx] = W[(long)(k0 + r) * Nc + n0 + lx];
    __syncthreads();
    #pragma unroll
    for (int r = ly; r < 32; r += 8)
        T[(long)(n0 + r) * K + k0 + lx] = __float2half_rn(t[lx][r]);
}

// ---------------------------------------------------------------------------
// fp16 flash attention. CTA = 128 queries of one (b,h) slice. 8 warps.
// S = Q K^T (single pass, Q pre-scaled by ATT_SCALE*log2e, exp2 softmax).
// O += P V   (single pass; P fp16 rounding error ~eps/sqrt(N_eff) — see R11
// theory). Keys 64/tile, 16 tiles, double-buffered single-barrier schedule.
// ---------------------------------------------------------------------------
#define AT_STRIDE 112                       // bytes per smem row (48 fp16 + pad)
#define AT_Q_BYTES (128 * AT_STRIDE)        // 14336
#define AT_T_BYTES (64 * AT_STRIDE)         // 7168
#define AT_STAGE (2 * AT_T_BYTES)           // 14336 (K, V)
#define ATT_SMEM (AT_Q_BYTES + 2 * AT_STAGE)   // 43008

__device__ __forceinline__ void at_stage(
    uint32_t sdst, const __half* kh, const __half* vh, int key0, int tid)
{
    for (int i = tid; i < 384; i += 256) {
        const int r = i / 6, c = i % 6;
        const uint32_t off = r * AT_STRIDE + c * 16;
        const long gm = (long)(key0 + r) * DH + c * 8;
        CP_ASYNC16(sdst + off,              kh + gm);
        CP_ASYNC16(sdst + AT_T_BYTES + off, vh + gm);
    }
}

__global__ __launch_bounds__(256)
void attn_mma(const __half* __restrict__ qkvhi,
              __half* __restrict__ Chi, __half* __restrict__ Clo)
{
    extern __shared__ char smem[];
    const uint32_t sb = smem_u32(smem);
    const int tid = threadIdx.x;
    const int wid = tid >> 5;
    const int lane = tid & 31;
    const int slice = blockIdx.y;
    const int q0 = blockIdx.x << 7;

    const long base = (long)(slice >> 4) * HEAD_BLK + (long)(slice & 15) * SLICE_SZ;
    const __half* qh = qkvhi + base + (long)q0 * DH;
    const __half* kh = qkvhi + THIRD + base;
    const __half* vh = qkvhi + 2L * THIRD + base;

    // group 0: Q tile
    for (int i = tid; i < 768; i += 256) {
        const int r = i / 6, c = i % 6;
        CP_ASYNC16(sb + r * AT_STRIDE + c * 16, qh + (long)r * DH + c * 8);
    }
    CP_COMMIT();
    // group 1: KV stage 0
    at_stage(sb + AT_Q_BYTES, kh, vh, 0, tid);
    CP_COMMIT();
    CP_WAIT1();          // Q retired (this thread)
    __syncthreads();     // Q visible to all

    // Q fragments (kept in regs, pre-scaled by ATT_SCALE*log2e)
    uint32_t qhf[3][4];
    {
        const int aRow = wid * 16 + ((lane >> 3) & 1) * 8 + (lane & 7);
        const int aColB = (lane >> 4) * 16;
        const __half2 qs = __float2half2_rn(QSCALE);
        #pragma unroll
        for (int ks = 0; ks < 3; ++ks) {
            uint32_t addr = sb + aRow * AT_STRIDE + aColB + ks * 32;
            LDSM_X4(qhf[ks][0], qhf[ks][1], qhf[ks][2], qhf[ks][3], addr);
            #pragma unroll
            for (int r = 0; r < 4; ++r) {
                __half2 v = *(__half2*)&qhf[ks][r];
                v = __hmul2(v, qs);
                qhf[ks][r] = *(uint32_t*)&v;
            }
        }
    }

    float m1 = -INFINITY, m2 = -INFINITY, l1 = 0.f, l2 = 0.f;
    float o[6][4];
    #pragma unroll
    for (int n = 0; n < 6; ++n)
        #pragma unroll
        for (int r = 0; r < 4; ++r) o[n][r] = 0.f;

    const int kpair = lane >> 3;
    const int kRowOff = (kpair >> 1) * 8 + (lane & 7);
    const int kColB = (kpair & 1) * 16;
    const int vRowOff = (lane & 7) + ((lane >> 3) & 1) * 8;

    for (int kt = 0; kt < 16; ++kt) {
        CP_WAIT0();        // stage kt retired (this thread)
        __syncthreads();   // stage-kt visible; compute kt-1 done everywhere
        if (kt + 1 < 16) {
            at_stage(sb + AT_Q_BYTES + ((kt + 1) & 1) * AT_STAGE,
                     kh, vh, (kt + 1) * 64, tid);
            CP_COMMIT();
        }

        const uint32_t stg = sb + AT_Q_BYTES + (kt & 1) * AT_STAGE;

        // ---- S = Q K^T (pre-scaled; log2 domain) ----
        float s[8][4];
        #pragma unroll
        for (int j = 0; j < 8; ++j)
            #pragma unroll
            for (int r = 0; r < 4; ++r) s[j][r] = 0.f;

        #pragma unroll
        for (int g = 0; g < 4; ++g) {
            #pragma unroll
            for (int ks = 0; ks < 3; ++ks) {
                const uint32_t ka = stg + (g * 16 + kRowOff) * AT_STRIDE
                                    + kColB + ks * 32;
                uint32_t kb[4];
                LDSM_X4(kb[0], kb[1], kb[2], kb[3], ka);
                MMA_F16(s[2 * g],     qhf[ks], kb);
                MMA_F16(s[2 * g + 1], qhf[ks], kb + 2);
            }
        }

        // ---- online softmax (exp2 domain) ----
        float mx1 = s[0][0], mx2 = s[0][2];
        #pragma unroll
        for (int j = 0; j < 8; ++j) {
            mx1 = fmaxf(mx1, fmaxf(s[j][0], s[j][1]));
            mx2 = fmaxf(mx2, fmaxf(s[j][2], s[j][3]));
        }
        mx1 = fmaxf(mx1, __shfl_xor_sync(0xffffffffu, mx1, 1));
        mx1 = fmaxf(mx1, __shfl_xor_sync(0xffffffffu, mx1, 2));
        mx2 = fmaxf(mx2, __shfl_xor_sync(0xffffffffu, mx2, 1));
        mx2 = fmaxf(mx2, __shfl_xor_sync(0xffffffffu, mx2, 2));

        const float nm1 = fmaxf(m1, mx1);
        const float nm2 = fmaxf(m2, mx2);
        const float e1 = ex2f(m1 - nm1);
        const float e2 = ex2f(m2 - nm2);
        m1 = nm1; m2 = nm2;

        float sum1 = 0.f, sum2 = 0.f;
        #pragma unroll
        for (int j = 0; j < 8; ++j) {
            s[j][0] = ex2f(s[j][0] - m1);
            s[j][1] = ex2f(s[j][1] - m1);
            s[j][2] = ex2f(s[j][2] - m2);
            s[j][3] = ex2f(s[j][3] - m2);
            sum1 += s[j][0] + s[j][1];
            sum2 += s[j][2] + s[j][3];
        }
        sum1 += __shfl_xor_sync(0xffffffffu, sum1, 1);
        sum1 += __shfl_xor_sync(0xffffffffu, sum1, 2);
        sum2 += __shfl_xor_sync(0xffffffffu, sum2, 1);
        sum2 += __shfl_xor_sync(0xffffffffu, sum2, 2);
        l1 = l1 * e1 + sum1;
        l2 = l2 * e2 + sum2;

        #pragma unroll
        for (int n = 0; n < 6; ++n) {
            o[n][0] *= e1; o[n][1] *= e1;
            o[n][2] *= e2; o[n][3] *= e2;
        }

        // ---- O += P V (single pass) ----
        #pragma unroll
        for (int kk = 0; kk < 4; ++kk) {
            uint32_t ph[4];
            ph[0] = packh2(s[2 * kk][0],     s[2 * kk][1]);
            ph[1] = packh2(s[2 * kk][2],     s[2 * kk][3]);
            ph[2] = packh2(s[2 * kk + 1][0], s[2 * kk + 1][1]);
            ph[3] = packh2(s[2 * kk + 1][2], s[2 * kk + 1][3]);

            const uint32_t vrowA = stg + AT_T_BYTES
                                   + (kk * 16 + vRowOff) * AT_STRIDE;
            #pragma unroll
            for (int n = 0; n < 6; ++n) {
                uint32_t vb[2];
                LDSM_X2T(vb[0], vb[1], vrowA + n * 16);
                MMA_F16(o[n], ph, vb);
            }
        }
    }

    // ---- epilogue: write context hi/lo at raw-reshape-flat offsets ----
    const float inv1 = 1.f / l1;
    const float inv2 = 1.f / l2;
    const long r1 = q0 + wid * 16 + (lane >> 2);
    const long r2 = r1 + 8;
    #pragma unroll
    for (int n = 0; n < 6; ++n) {
        const int col = n * 8 + (lane & 3) * 2;
        float ra, rb;
        uint32_t h0 = packh_hi(o[n][0] * inv1, o[n][1] * inv1, ra, rb);
        *(uint32_t*)(Chi + base + r1 * DH + col) = h0;
        *(uint32_t*)(Clo + base + r1 * DH + col) = packh2(ra, rb);
        uint32_t h1 = packh_hi(o[n][2] * inv2, o[n][3] * inv2, ra, rb);
        *(uint32_t*)(Chi + base + r2 * DH + col) = h1;
        *(uint32_t*)(Clo + base + r2 * DH + col) = packh2(ra, rb);
    }
}

// ---------------------------------------------------------------------------
extern "C" void kernel_launch(void* const* d_in, const int* in_sizes, int n_in,
                              void* d_out, int out_size)
{
    (void)in_sizes; (void)n_in; (void)out_size;
    const float* x    = (const float*)d_in[0];
    const float* Wqkv = (const float*)d_in[1];
    const float* Wo   = (const float*)d_in[2];
    const float* bo   = (const float*)d_in[3];
    float* out = (float*)d_out;

    void *qkvhi, *xhi, *xlo, *chi, *clo, *wqh, *woh;
    cudaGetSymbolAddress(&qkvhi, g_qkvhi);
    cudaGetSymbolAddress(&xhi, g_xhi);
    cudaGetSymbolAddress(&xlo, g_xlo);
    cudaGetSymbolAddress(&chi, g_chi);
    cudaGetSymbolAddress(&clo, g_clo);
    cudaGetSymbolAddress(&wqh, g_wqh);
    cudaGetSymbolAddress(&woh, g_woh);

    cudaFuncSetAttribute(mma_gemm, cudaFuncAttributeMaxDynamicSharedMemorySize,
                         GEMM_SMEM);
    cudaFuncSetAttribute(attn_mma, cudaFuncAttributeMaxDynamicSharedMemorySize,
                         ATT_SMEM);

    // prep: split x (hi/lo fp16), transpose weights to single fp16
    split_kernel<<<(ROWS * DIMM + 255) / 256, 256>>>(
        x, (__half*)xhi, (__half*)xlo, ROWS * DIMM);
    tsingle_kernel<<<dim3(QKVC / 32, DIMM / 32), 256>>>(
        Wqkv, (__half*)wqh, DIMM, QKVC);
    tsingle_kernel<<<dim3(DIMM / 32, DIMM / 32), 256>>>(
        Wo, (__half*)woh, DIMM, DIMM);

    // 1) QKV projection -> fp16 qkv
    mma_gemm<<<dim3(QKVC / 128, ROWS / 128), 256, GEMM_SMEM>>>(
        (const __half*)xhi, (const __half*)xlo, (const __half*)wqh,
        nullptr, nullptr, (__half*)qkvhi,
        ROWS, QKVC, DIMM);

    // 2) fp16 flash attention -> context hi/lo
    attn_mma<<<dim3(NSEQ / 128, NB * HEADS), 256, ATT_SMEM>>>(
        (const __half*)qkvhi, (__half*)chi, (__half*)clo);

    // 3) output projection (+bias) -> fp32 out
    mma_gemm<<<dim3(DIMM / 128, ROWS / 128), 256, GEMM_SMEM>>>(
        (const __half*)chi, (const __half*)clo, (const __half*)woh,
        bo, out, nullptr,
        ROWS, DIMM, DIMM);
}

// round 13
// speedup vs baseline: 1.4951x; 1.2448x over previous
#include <cuda_runtime.h>
#include <cuda_fp16.h>
#include <math.h>
#include <stdint.h>

#define DIMM 768
#define HEADS 16
#define DH 48
#define NB 8
#define NSEQ 1024
#define ROWS 8192            // NB*NSEQ
#define QKVC 2304            // 3*DIMM
#define SLICE_SZ 49152       // NSEQ*DH
#define HEAD_BLK 786432      // HEADS*NSEQ*DH
#define THIRD 6291456        // NB*HEAD_BLK
// Q pre-scale: ATT_SCALE * log2(e) folded into Q fragments; softmax uses ex2.
#define QSCALE 0.20823030778170076f

// ---------------- scratch (__device__ globals; no allocation allowed) ------
__device__ __half g_qkvhi[ROWS * QKVC];      // qkv fp16 (GEMM1 out)
__device__ __half g_xh[ROWS * DIMM];         // x fp16 (single precision)
__device__ __half g_chi[ROWS * DIMM];        // context hi (attn out)
__device__ __half g_clo[ROWS * DIMM];        // context lo residual
__device__ __half g_wqh[QKVC * DIMM];        // Wqkv^T fp16 [2304,768]
__device__ __half g_woh[DIMM * DIMM];        // Wo^T fp16   [768,768]

// ---------------- PTX helpers (arch-agnostic: sm_80+ features only) --------
__device__ __forceinline__ uint32_t smem_u32(const void* p) {
    uint32_t a;
    asm("{ .reg .u64 t; cvta.to.shared.u64 t, %1; cvt.u32.u64 %0, t; }"
        : "=r"(a) : "l"(p));
    return a;
}
__device__ __forceinline__ float ex2f(float x) {
    float r;
    asm("ex2.approx.ftz.f32 %0, %1;" : "=f"(r) : "f"(x));
    return r;
}
#define LDSM_X4(r0, r1, r2, r3, addr) \
    asm volatile("ldmatrix.sync.aligned.m8n8.x4.shared.b16 {%0,%1,%2,%3}, [%4];" \
                 : "=r"(r0), "=r"(r1), "=r"(r2), "=r"(r3) : "r"(addr))
#define LDSM_X2(r0, r1, addr) \
    asm volatile("ldmatrix.sync.aligned.m8n8.x2.shared.b16 {%0,%1}, [%2];" \
                 : "=r"(r0), "=r"(r1) : "r"(addr))
#define LDSM_X2T(r0, r1, addr) \
    asm volatile("ldmatrix.sync.aligned.m8n8.x2.trans.shared.b16 {%0,%1}, [%2];" \
                 : "=r"(r0), "=r"(r1) : "r"(addr))
#define MMA_F16(c, a, b) \
    asm volatile("mma.sync.aligned.m16n8k16.row.col.f32.f16.f16.f32 " \
                 "{%0,%1,%2,%3},{%4,%5,%6,%7},{%8,%9},{%0,%1,%2,%3};" \
                 : "+f"((c)[0]), "+f"((c)[1]), "+f"((c)[2]), "+f"((c)[3]) \
                 : "r"((a)[0]), "r"((a)[1]), "r"((a)[2]), "r"((a)[3]), \
                   "r"((b)[0]), "r"((b)[1]))
#define CP_ASYNC16(s, g) \
    asm volatile("cp.async.cg.shared.global [%0], [%1], 16;" :: "r"(s), "l"(g))
#define CP_COMMIT() asm volatile("cp.async.commit_group;" ::: "memory")
#define CP_WAIT1()  asm volatile("cp.async.wait_group 1;" ::: "memory")
#define CP_WAIT0()  asm volatile("cp.async.wait_group 0;" ::: "memory")

__device__ __forceinline__ uint32_t packh_hi(float a, float b, float& ra, float& rb) {
    __half2 t;
    t.x = __float2half_rn(a);
    t.y = __float2half_rn(b);
    ra = a - __half2float(t.x);
    rb = b - __half2float(t.y);
    return *(uint32_t*)&t;
}
__device__ __forceinline__ uint32_t packh2(float a, float b) {
    __half2 t;
    t.x = __float2half_rn(a);
    t.y = __float2half_rn(b);
    return *(uint32_t*)&t;
}

// ---------------------------------------------------------------------------
// fp16 GEMM on mma.sync: C = (Ahi [+ Alo]) @ B^T (+bias).
// BM=BN=128, BK=32, 8 warps, up to 3 tiles/stage (Ahi, Alo, B), 3-stage
// pipeline. If Alo == nullptr the lo tile load and lo MMA pass are skipped
// (single-pass mode, used by GEMM1 where x is pre-rounded to fp16).
// ---------------------------------------------------------------------------
#define BK 32
#define ROW_BYTES 80
#define TILE_BYTES (128 * ROW_BYTES)       // 10240
#define STAGE_BYTES (3 * TILE_BYTES)       // 30720 (Ahi, Alo, B)
#define NSTAGE 3
#define GEMM_SMEM (NSTAGE * STAGE_BYTES)   // 92160

__device__ __forceinline__ void stage_load(
    uint32_t sbyte, const __half* s0, const __half* s1, const __half* s2,
    int K, long kOff, int tid)
{
    const __half* srcs[3] = {s0, s1, s2};
    #pragma unroll
    for (int m = 0; m < 3; ++m) {
        if (m == 1 && s1 == nullptr) continue;   // uniform skip in single-A mode
        #pragma unroll
        for (int t = 0; t < 2; ++t) {
            const int ch = tid * 2 + t;          // 0..511
            const int row = ch >> 2;
            const int cc = ch & 3;
            const void* g = srcs[m] + (long)row * K + kOff + cc * 8;
            uint32_t s = sbyte + m * TILE_BYTES + row * ROW_BYTES + cc * 16;
            CP_ASYNC16(s, g);
        }
    }
}

__global__ __launch_bounds__(256, 2)
void mma_gemm(const __half* __restrict__ Ahi, const __half* __restrict__ Alo,
              const __half* __restrict__ B,
              const float* __restrict__ bias, float* __restrict__ C,
              __half* __restrict__ Ohi,
              int M, int Nc, int K)
{
    extern __shared__ char smem[];
    const uint32_t sb = smem_u32(smem);
    const int tid = threadIdx.x;
    const int wid = tid >> 5;
    const int lane = tid & 31;
    const int wr = wid >> 2;
    const int wc = wid & 3;
    const int rowBase = blockIdx.y << 7;
    const int colBase = blockIdx.x << 7;
    const int nch = K / BK;
    const bool hasLo = (Alo != nullptr);

    const __half* pAhi = Ahi + (long)rowBase * K;
    const __half* pAlo = hasLo ? (Alo + (long)rowBase * K) : nullptr;
    const __half* pB   = B + (long)colBase * K;

    const int r8 = lane & 7;
    const int quad = lane >> 3;
    const int aRow = wr * 64 + (quad & 1) * 8 + r8;
    const int aColB = ((quad >> 1) * 8) * 2;
    const int bRow = wc * 32 + (lane & 7);
    const int bColB = (((lane >> 3) & 1) * 8) * 2;

    float acc[4][4][4];
    #pragma unroll
    for (int i = 0; i < 4; ++i)
        #pragma unroll
        for (int j = 0; j < 4; ++j)
            #pragma unroll
            for (int r = 0; r < 4; ++r) acc[i][j][r] = 0.f;

    // prologue: stages 0, 1 in flight
    stage_load(sb, pAhi, pAlo, pB, K, 0, tid);
    CP_COMMIT();
    stage_load(sb + STAGE_BYTES, pAhi, pAlo, pB, K, BK, tid);
    CP_COMMIT();

    for (int c = 0; c < nch; ++c) {
        if (c + 1 < nch) { CP_WAIT1(); } else { CP_WAIT0(); }  // stage c retired
        __syncthreads();   // stage-c visible to all; compute c-1 done everywhere
        if (c + 2 < nch) { // slot (c+2)%NSTAGE freed (last read at compute c-1)
            stage_load(sb + ((c + 2) % NSTAGE) * STAGE_BYTES, pAhi, pAlo, pB,
                       K, (long)(c + 2) * BK, tid);
            CP_COMMIT();
        }

        const uint32_t stg = sb + (c % NSTAGE) * STAGE_BYTES;
        #pragma unroll
        for (int ks = 0; ks < 2; ++ks) {
            uint32_t ah[4][4];
            #pragma unroll
            for (int i = 0; i < 4; ++i) {
                uint32_t aoff = stg + (aRow + i * 16) * ROW_BYTES + aColB + ks * 32;
                LDSM_X4(ah[i][0], ah[i][1], ah[i][2], ah[i][3], aoff);
            }
            uint32_t bfr[4][2];
            #pragma unroll
            for (int j = 0; j < 4; ++j) {
                uint32_t boff = stg + 2 * TILE_BYTES + (bRow + j * 8) * ROW_BYTES
                                + bColB + ks * 32;
                LDSM_X2(bfr[j][0], bfr[j][1], boff);
            }
            #pragma unroll
            for (int i = 0; i < 4; ++i)
                #pragma unroll
                for (int j = 0; j < 4; ++j)
                    MMA_F16(acc[i][j], ah[i], bfr[j]);
            if (hasLo) {
                uint32_t al[4][4];
                #pragma unroll
                for (int i = 0; i < 4; ++i) {
                    uint32_t aoff = stg + (aRow + i * 16) * ROW_BYTES + aColB
                                    + ks * 32 + TILE_BYTES;
                    LDSM_X4(al[i][0], al[i][1], al[i][2], al[i][3], aoff);
                }
                #pragma unroll
                for (int i = 0; i < 4; ++i)
                    #pragma unroll
                    for (int j = 0; j < 4; ++j)
                        MMA_F16(acc[i][j], al[i], bfr[j]);
            }
        }
    }

    #pragma unroll
    for (int i = 0; i < 4; ++i) {
        const long r0 = rowBase + wr * 64 + i * 16 + (lane >> 2);
        #pragma unroll
        for (int j = 0; j < 4; ++j) {
            const int col = wc * 32 + j * 8 + (lane & 3) * 2;
            if (Ohi != nullptr) {
                *(uint32_t*)(Ohi + r0 * Nc + colBase + col) =
                    packh2(acc[i][j][0], acc[i][j][1]);
                *(uint32_t*)(Ohi + (r0 + 8) * Nc + colBase + col) =
                    packh2(acc[i][j][2], acc[i][j][3]);
            } else {
                float b0 = 0.f, b1 = 0.f;
                if (bias != nullptr) {
                    b0 = bias[colBase + col];
                    b1 = bias[colBase + col + 1];
                }
                *(float2*)(C + r0 * Nc + colBase + col) =
                    make_float2(acc[i][j][0] + b0, acc[i][j][1] + b1);
                *(float2*)(C + (r0 + 8) * Nc + colBase + col) =
                    make_float2(acc[i][j][2] + b0, acc[i][j][3] + b1);
            }
        }
    }
}

// ---------------------------------------------------------------------------
// prep kernels
// ---------------------------------------------------------------------------
__global__ __launch_bounds__(256)
void round_kernel(const float* __restrict__ src, __half* __restrict__ dst, int n)
{
    int i = blockIdx.x * 256 + threadIdx.x;
    if (i < n) dst[i] = __float2half_rn(src[i]);
}

// W[K,Nc] -> W^T[Nc,K] single fp16
__global__ __launch_bounds__(256)
void tsingle_kernel(const float* __restrict__ W, __half* __restrict__ T,
                    int K, int Nc)
{
    __shared__ float t[32][33];
    const int n0 = blockIdx.x * 32;
    const int k0 = blockIdx.y * 32;
    const int lx = threadIdx.x & 31;
    const int ly = threadIdx.x >> 5;
    #pragma unroll
    for (int r = ly; r < 32; r += 8)
        t[r][lx] = W[(long)(k0 + r) * Nc + n0 + lx];
    __syncthreads();
    #pragma unroll
    for (int r = ly; r < 32; r += 8)
        T[(long)(n0 + r) * K + k0 + lx] = __float2half_rn(t[lx][r]);
}

// ---------------------------------------------------------------------------
// fp16 flash attention. CTA = 128 queries of one (b,h) slice. 8 warps.
// S = Q K^T (single pass, Q pre-scaled by ATT_SCALE*log2e, exp2 softmax).
// O += P V (single pass). Keys 64/tile, 16 tiles, double-buffered.
// ---------------------------------------------------------------------------
#define AT_STRIDE 112                       // bytes per smem row (48 fp16 + pad)
#define AT_Q_BYTES (128 * AT_STRIDE)        // 14336
#define AT_T_BYTES (64 * AT_STRIDE)         // 7168
#define AT_STAGE (2 * AT_T_BYTES)           // 14336 (K, V)
#define ATT_SMEM (AT_Q_BYTES + 2 * AT_STAGE)   // 43008

__device__ __forceinline__ void at_stage(
    uint32_t sdst, const __half* kh, const __half* vh, int key0, int tid)
{
    for (int i = tid; i < 384; i += 256) {
        const int r = i / 6, c = i % 6;
        const uint32_t off = r * AT_STRIDE + c * 16;
        const long gm = (long)(key0 + r) * DH + c * 8;
        CP_ASYNC16(sdst + off,              kh + gm);
        CP_ASYNC16(sdst + AT_T_BYTES + off, vh + gm);
    }
}

__global__ __launch_bounds__(256)
void attn_mma(const __half* __restrict__ qkvhi,
              __half* __restrict__ Chi, __half* __restrict__ Clo)
{
    extern __shared__ char smem[];
    const uint32_t sb = smem_u32(smem);
    const int tid = threadIdx.x;
    const int wid = tid >> 5;
    const int lane = tid & 31;
    const int slice = blockIdx.y;
    const int q0 = blockIdx.x << 7;

    const long base = (long)(slice >> 4) * HEAD_BLK + (long)(slice & 15) * SLICE_SZ;
    const __half* qh = qkvhi + base + (long)q0 * DH;
    const __half* kh = qkvhi + THIRD + base;
    const __half* vh = qkvhi + 2L * THIRD + base;

    // group 0: Q tile
    for (int i = tid; i < 768; i += 256) {
        const int r = i / 6, c = i % 6;
        CP_ASYNC16(sb + r * AT_STRIDE + c * 16, qh + (long)r * DH + c * 8);
    }
    CP_COMMIT();
    // group 1: KV stage 0
    at_stage(sb + AT_Q_BYTES, kh, vh, 0, tid);
    CP_COMMIT();
    CP_WAIT1();          // Q retired (this thread)
    __syncthreads();     // Q visible to all

    // Q fragments (kept in regs, pre-scaled by ATT_SCALE*log2e)
    uint32_t qhf[3][4];
    {
        const int aRow = wid * 16 + ((lane >> 3) & 1) * 8 + (lane & 7);
        const int aColB = (lane >> 4) * 16;
        const __half2 qs = __float2half2_rn(QSCALE);
        #pragma unroll
        for (int ks = 0; ks < 3; ++ks) {
            uint32_t addr = sb + aRow * AT_STRIDE + aColB + ks * 32;
            LDSM_X4(qhf[ks][0], qhf[ks][1], qhf[ks][2], qhf[ks][3], addr);
            #pragma unroll
            for (int r = 0; r < 4; ++r) {
                __half2 v = *(__half2*)&qhf[ks][r];
                v = __hmul2(v, qs);
                qhf[ks][r] = *(uint32_t*)&v;
            }
        }
    }

    float m1 = -INFINITY, m2 = -INFINITY, l1 = 0.f, l2 = 0.f;
    float o[6][4];
    #pragma unroll
    for (int n = 0; n < 6; ++n)
        #pragma unroll
        for (int r = 0; r < 4; ++r) o[n][r] = 0.f;

    const int kpair = lane >> 3;
    const int kRowOff = (kpair >> 1) * 8 + (lane & 7);
    const int kColB = (kpair & 1) * 16;
    const int vRowOff = (lane & 7) + ((lane >> 3) & 1) * 8;

    for (int kt = 0; kt < 16; ++kt) {
        CP_WAIT0();        // stage kt retired (this thread)
        __syncthreads();   // stage-kt visible; compute kt-1 done everywhere
        if (kt + 1 < 16) {
            at_stage(sb + AT_Q_BYTES + ((kt + 1) & 1) * AT_STAGE,
                     kh, vh, (kt + 1) * 64, tid);
            CP_COMMIT();
        }

        const uint32_t stg = sb + AT_Q_BYTES + (kt & 1) * AT_STAGE;

        // ---- S = Q K^T (pre-scaled; log2 domain) ----
        float s[8][4];
        #pragma unroll
        for (int j = 0; j < 8; ++j)
            #pragma unroll
            for (int r = 0; r < 4; ++r) s[j][r] = 0.f;

        #pragma unroll
        for (int g = 0; g < 4; ++g) {
            #pragma unroll
            for (int ks = 0; ks < 3; ++ks) {
                const uint32_t ka = stg + (g * 16 + kRowOff) * AT_STRIDE
                                    + kColB + ks * 32;
                uint32_t kb[4];
                LDSM_X4(kb[0], kb[1], kb[2], kb[3], ka);
                MMA_F16(s[2 * g],     qhf[ks], kb);
                MMA_F16(s[2 * g + 1], qhf[ks], kb + 2);
            }
        }

        // ---- online softmax (exp2 domain) ----
        float mx1 = s[0][0], mx2 = s[0][2];
        #pragma unroll
        for (int j = 0; j < 8; ++j) {
            mx1 = fmaxf(mx1, fmaxf(s[j][0], s[j][1]));
            mx2 = fmaxf(mx2, fmaxf(s[j][2], s[j][3]));
        }
        mx1 = fmaxf(mx1, __shfl_xor_sync(0xffffffffu, mx1, 1));
        mx1 = fmaxf(mx1, __shfl_xor_sync(0xffffffffu, mx1, 2));
        mx2 = fmaxf(mx2, __shfl_xor_sync(0xffffffffu, mx2, 1));
        mx2 = fmaxf(mx2, __shfl_xor_sync(0xffffffffu, mx2, 2));

        const float nm1 = fmaxf(m1, mx1);
        const float nm2 = fmaxf(m2, mx2);
        const float e1 = ex2f(m1 - nm1);
        const float e2 = ex2f(m2 - nm2);
        m1 = nm1; m2 = nm2;

        float sum1 = 0.f, sum2 = 0.f;
        #pragma unroll
        for (int j = 0; j < 8; ++j) {
            s[j][0] = ex2f(s[j][0] - m1);
            s[j][1] = ex2f(s[j][1] - m1);
            s[j][2] = ex2f(s[j][2] - m2);
            s[j][3] = ex2f(s[j][3] - m2);
            sum1 += s[j][0] + s[j][1];
            sum2 += s[j][2] + s[j][3];
        }
        sum1 += __shfl_xor_sync(0xffffffffu, sum1, 1);
        sum1 += __shfl_xor_sync(0xffffffffu, sum1, 2);
        sum2 += __shfl_xor_sync(0xffffffffu, sum2, 1);
        sum2 += __shfl_xor_sync(0xffffffffu, sum2, 2);
        l1 = l1 * e1 + sum1;
        l2 = l2 * e2 + sum2;

        #pragma unroll
        for (int n = 0; n < 6; ++n) {
            o[n][0] *= e1; o[n][1] *= e1;
            o[n][2] *= e2; o[n][3] *= e2;
        }

        // ---- O += P V (single pass) ----
        #pragma unroll
        for (int kk = 0; kk < 4; ++kk) {
            uint32_t ph[4];
            ph[0] = packh2(s[2 * kk][0],     s[2 * kk][1]);
            ph[1] = packh2(s[2 * kk][2],     s[2 * kk][3]);
            ph[2] = packh2(s[2 * kk + 1][0], s[2 * kk + 1][1]);
            ph[3] = packh2(s[2 * kk + 1][2], s[2 * kk + 1][3]);

            const uint32_t vrowA = stg + AT_T_BYTES
                                   + (kk * 16 + vRowOff) * AT_STRIDE;
            #pragma unroll
            for (int n = 0; n < 6; ++n) {
                uint32_t vb[2];
                LDSM_X2T(vb[0], vb[1], vrowA + n * 16);
                MMA_F16(o[n], ph, vb);
            }
        }
    }

    // ---- epilogue: write context hi/lo at raw-reshape-flat offsets ----
    const float inv1 = 1.f / l1;
    const float inv2 = 1.f / l2;
    const long r1 = q0 + wid * 16 + (lane >> 2);
    const long r2 = r1 + 8;
    #pragma unroll
    for (int n = 0; n < 6; ++n) {
        const int col = n * 8 + (lane & 3) * 2;
        float ra, rb;
        uint32_t h0 = packh_hi(o[n][0] * inv1, o[n][1] * inv1, ra, rb);
        *(uint32_t*)(Chi + base + r1 * DH + col) = h0;
        *(uint32_t*)(Clo + base + r1 * DH + col) = packh2(ra, rb);
        uint32_t h1 = packh_hi(o[n][2] * inv2, o[n][3] * inv2, ra, rb);
        *(uint32_t*)(Chi + base + r2 * DH + col) = h1;
        *(uint32_t*)(Clo + base + r2 * DH + col) = packh2(ra, rb);
    }
}

// ---------------------------------------------------------------------------
extern "C" void kernel_launch(void* const* d_in, const int* in_sizes, int n_in,
                              void* d_out, int out_size)
{
    (void)in_sizes; (void)n_in; (void)out_size;
    const float* x    = (const float*)d_in[0];
    const float* Wqkv = (const float*)d_in[1];
    const float* Wo   = (const float*)d_in[2];
    const float* bo   = (const float*)d_in[3];
    float* out = (float*)d_out;

    void *qkvhi, *xh, *chi, *clo, *wqh, *woh;
    cudaGetSymbolAddress(&qkvhi, g_qkvhi);
    cudaGetSymbolAddress(&xh, g_xh);
    cudaGetSymbolAddress(&chi, g_chi);
    cudaGetSymbolAddress(&clo, g_clo);
    cudaGetSymbolAddress(&wqh, g_wqh);
    cudaGetSymbolAddress(&woh, g_woh);

    cudaFuncSetAttribute(mma_gemm, cudaFuncAttributeMaxDynamicSharedMemorySize,
                         GEMM_SMEM);
    cudaFuncSetAttribute(attn_mma, cudaFuncAttributeMaxDynamicSharedMemorySize,
                         ATT_SMEM);

    // prep: round x to fp16, transpose weights to single fp16
    round_kernel<<<(ROWS * DIMM + 255) / 256, 256>>>(
        x, (__half*)xh, ROWS * DIMM);
    tsingle_kernel<<<dim3(QKVC / 32, DIMM / 32), 256>>>(
        Wqkv, (__half*)wqh, DIMM, QKVC);
    tsingle_kernel<<<dim3(DIMM / 32, DIMM / 32), 256>>>(
        Wo, (__half*)woh, DIMM, DIMM);

    // 1) QKV projection (single-pass fp16) -> fp16 qkv
    mma_gemm<<<dim3(QKVC / 128, ROWS / 128), 256, GEMM_SMEM>>>(
        (const __half*)xh, nullptr, (const __half*)wqh,
        nullptr, nullptr, (__half*)qkvhi,
        ROWS, QKVC, DIMM);

    // 2) fp16 flash attention -> context hi/lo
    attn_mma<<<dim3(NSEQ / 128, NB * HEADS), 256, ATT_SMEM>>>(
        (const __half*)qkvhi, (__half*)chi, (__half*)clo);

    // 3) output projection (split ctx, +bias) -> fp32 out
    mma_gemm<<<dim3(DIMM / 128, ROWS / 128), 256, GEMM_SMEM>>>(
        (const __half*)chi, (const __half*)clo, (const __half*)woh,
        bo, out, nullptr,
        ROWS, DIMM, DIMM);
}

// round 14
// speedup vs baseline: 1.6563x; 1.1078x over previous
#include <cuda_runtime.h>
#include <cuda_fp16.h>
#include <math.h>
#include <stdint.h>

#define DIMM 768
#define HEADS 16
#define DH 48
#define NB 8
#define NSEQ 1024
#define ROWS 8192            // NB*NSEQ
#define QKVC 2304            // 3*DIMM
#define SLICE_SZ 49152       // NSEQ*DH
#define HEAD_BLK 786432      // HEADS*NSEQ*DH
#define THIRD 6291456        // NB*HEAD_BLK
// Q pre-scale: ATT_SCALE * log2(e) folded into Q fragments; softmax uses ex2.
#define QSCALE 0.20823030778170076f

// ---------------- scratch (__device__ globals; no allocation allowed) ------
__device__ __half g_qkvhi[ROWS * QKVC];      // qkv fp16 (GEMM1 out)
__device__ __half g_xh[ROWS * DIMM];         // x fp16 (single precision)
__device__ __half g_ch[ROWS * DIMM];         // context fp16 (attn out)
__device__ __half g_wqh[QKVC * DIMM];        // Wqkv^T fp16 [2304,768]
__device__ __half g_woh[DIMM * DIMM];        // Wo^T fp16   [768,768]

// ---------------- PTX helpers (arch-agnostic: sm_80+ features only) --------
__device__ __forceinline__ uint32_t smem_u32(const void* p) {
    uint32_t a;
    asm("{ .reg .u64 t; cvta.to.shared.u64 t, %1; cvt.u32.u64 %0, t; }"
        : "=r"(a) : "l"(p));
    return a;
}
__device__ __forceinline__ float ex2f(float x) {
    float r;
    asm("ex2.approx.ftz.f32 %0, %1;" : "=f"(r) : "f"(x));
    return r;
}
#define LDSM_X4(r0, r1, r2, r3, addr) \
    asm volatile("ldmatrix.sync.aligned.m8n8.x4.shared.b16 {%0,%1,%2,%3}, [%4];" \
                 : "=r"(r0), "=r"(r1), "=r"(r2), "=r"(r3) : "r"(addr))
#define LDSM_X2(r0, r1, addr) \
    asm volatile("ldmatrix.sync.aligned.m8n8.x2.shared.b16 {%0,%1}, [%2];" \
                 : "=r"(r0), "=r"(r1) : "r"(addr))
#define LDSM_X2T(r0, r1, addr) \
    asm volatile("ldmatrix.sync.aligned.m8n8.x2.trans.shared.b16 {%0,%1}, [%2];" \
                 : "=r"(r0), "=r"(r1) : "r"(addr))
#define MMA_F16(c, a, b) \
    asm volatile("mma.sync.aligned.m16n8k16.row.col.f32.f16.f16.f32 " \
                 "{%0,%1,%2,%3},{%4,%5,%6,%7},{%8,%9},{%0,%1,%2,%3};" \
                 : "+f"((c)[0]), "+f"((c)[1]), "+f"((c)[2]), "+f"((c)[3]) \
                 : "r"((a)[0]), "r"((a)[1]), "r"((a)[2]), "r"((a)[3]), \
                   "r"((b)[0]), "r"((b)[1]))
#define CP_ASYNC16(s, g) \
    asm volatile("cp.async.cg.shared.global [%0], [%1], 16;" :: "r"(s), "l"(g))
#define CP_COMMIT() asm volatile("cp.async.commit_group;" ::: "memory")
#define CP_WAIT1()  asm volatile("cp.async.wait_group 1;" ::: "memory")
#define CP_WAIT0()  asm volatile("cp.async.wait_group 0;" ::: "memory")

__device__ __forceinline__ uint32_t packh2(float a, float b) {
    __half2 t;
    t.x = __float2half_rn(a);
    t.y = __float2half_rn(b);
    return *(uint32_t*)&t;
}

// ---------------------------------------------------------------------------
// fp16 GEMM on mma.sync: C = (Ahi [+ Alo]) @ B^T (+bias).
// BM=BN=128, BK=32, 8 warps, up to 3 tiles/stage (Ahi, Alo, B), 3-stage
// pipeline. If Alo == nullptr the lo tile load and lo MMA pass are skipped.
// ---------------------------------------------------------------------------
#define BK 32
#define ROW_BYTES 80
#define TILE_BYTES (128 * ROW_BYTES)       // 10240
#define STAGE_BYTES (3 * TILE_BYTES)       // 30720 (Ahi, Alo, B)
#define NSTAGE 3
#define GEMM_SMEM (NSTAGE * STAGE_BYTES)   // 92160

__device__ __forceinline__ void stage_load(
    uint32_t sbyte, const __half* s0, const __half* s1, const __half* s2,
    int K, long kOff, int tid)
{
    const __half* srcs[3] = {s0, s1, s2};
    #pragma unroll
    for (int m = 0; m < 3; ++m) {
        if (m == 1 && s1 == nullptr) continue;   // uniform skip in single-A mode
        #pragma unroll
        for (int t = 0; t < 2; ++t) {
            const int ch = tid * 2 + t;          // 0..511
            const int row = ch >> 2;
            const int cc = ch & 3;
            const void* g = srcs[m] + (long)row * K + kOff + cc * 8;
            uint32_t s = sbyte + m * TILE_BYTES + row * ROW_BYTES + cc * 16;
            CP_ASYNC16(s, g);
        }
    }
}

__global__ __launch_bounds__(256, 2)
void mma_gemm(const __half* __restrict__ Ahi, const __half* __restrict__ Alo,
              const __half* __restrict__ B,
              const float* __restrict__ bias, float* __restrict__ C,
              __half* __restrict__ Ohi,
              int M, int Nc, int K)
{
    extern __shared__ char smem[];
    const uint32_t sb = smem_u32(smem);
    const int tid = threadIdx.x;
    const int wid = tid >> 5;
    const int lane = tid & 31;
    const int wr = wid >> 2;
    const int wc = wid & 3;
    const int rowBase = blockIdx.y << 7;
    const int colBase = blockIdx.x << 7;
    const int nch = K / BK;
    const bool hasLo = (Alo != nullptr);

    const __half* pAhi = Ahi + (long)rowBase * K;
    const __half* pAlo = hasLo ? (Alo + (long)rowBase * K) : nullptr;
    const __half* pB   = B + (long)colBase * K;

    const int r8 = lane & 7;
    const int quad = lane >> 3;
    const int aRow = wr * 64 + (quad & 1) * 8 + r8;
    const int aColB = ((quad >> 1) * 8) * 2;
    const int bRow = wc * 32 + (lane & 7);
    const int bColB = (((lane >> 3) & 1) * 8) * 2;

    float acc[4][4][4];
    #pragma unroll
    for (int i = 0; i < 4; ++i)
        #pragma unroll
        for (int j = 0; j < 4; ++j)
            #pragma unroll
            for (int r = 0; r < 4; ++r) acc[i][j][r] = 0.f;

    // prologue: stages 0, 1 in flight
    stage_load(sb, pAhi, pAlo, pB, K, 0, tid);
    CP_COMMIT();
    stage_load(sb + STAGE_BYTES, pAhi, pAlo, pB, K, BK, tid);
    CP_COMMIT();

    for (int c = 0; c < nch; ++c) {
        if (c + 1 < nch) { CP_WAIT1(); } else { CP_WAIT0(); }  // stage c retired
        __syncthreads();   // stage-c visible to all; compute c-1 done everywhere
        if (c + 2 < nch) { // slot (c+2)%NSTAGE freed (last read at compute c-1)
            stage_load(sb + ((c + 2) % NSTAGE) * STAGE_BYTES, pAhi, pAlo, pB,
                       K, (long)(c + 2) * BK, tid);
            CP_COMMIT();
        }

        const uint32_t stg = sb + (c % NSTAGE) * STAGE_BYTES;
        #pragma unroll
        for (int ks = 0; ks < 2; ++ks) {
            uint32_t ah[4][4];
            #pragma unroll
            for (int i = 0; i < 4; ++i) {
                uint32_t aoff = stg + (aRow + i * 16) * ROW_BYTES + aColB + ks * 32;
                LDSM_X4(ah[i][0], ah[i][1], ah[i][2], ah[i][3], aoff);
            }
            uint32_t bfr[4][2];
            #pragma unroll
            for (int j = 0; j < 4; ++j) {
                uint32_t boff = stg + 2 * TILE_BYTES + (bRow + j * 8) * ROW_BYTES
                                + bColB + ks * 32;
                LDSM_X2(bfr[j][0], bfr[j][1], boff);
            }
            #pragma unroll
            for (int i = 0; i < 4; ++i)
                #pragma unroll
                for (int j = 0; j < 4; ++j)
                    MMA_F16(acc[i][j], ah[i], bfr[j]);
            if (hasLo) {
                uint32_t al[4][4];
                #pragma unroll
                for (int i = 0; i < 4; ++i) {
                    uint32_t aoff = stg + (aRow + i * 16) * ROW_BYTES + aColB
                                    + ks * 32 + TILE_BYTES;
                    LDSM_X4(al[i][0], al[i][1], al[i][2], al[i][3], aoff);
                }
                #pragma unroll
                for (int i = 0; i < 4; ++i)
                    #pragma unroll
                    for (int j = 0; j < 4; ++j)
                        MMA_F16(acc[i][j], al[i], bfr[j]);
            }
        }
    }

    #pragma unroll
    for (int i = 0; i < 4; ++i) {
        const long r0 = rowBase + wr * 64 + i * 16 + (lane >> 2);
        #pragma unroll
        for (int j = 0; j < 4; ++j) {
            const int col = wc * 32 + j * 8 + (lane & 3) * 2;
            if (Ohi != nullptr) {
                *(uint32_t*)(Ohi + r0 * Nc + colBase + col) =
                    packh2(acc[i][j][0], acc[i][j][1]);
                *(uint32_t*)(Ohi + (r0 + 8) * Nc + colBase + col) =
                    packh2(acc[i][j][2], acc[i][j][3]);
            } else {
                float b0 = 0.f, b1 = 0.f;
                if (bias != nullptr) {
                    b0 = bias[colBase + col];
                    b1 = bias[colBase + col + 1];
                }
                *(float2*)(C + r0 * Nc + colBase + col) =
                    make_float2(acc[i][j][0] + b0, acc[i][j][1] + b1);
                *(float2*)(C + (r0 + 8) * Nc + colBase + col) =
                    make_float2(acc[i][j][2] + b0, acc[i][j][3] + b1);
            }
        }
    }
}

// ---------------------------------------------------------------------------
// prep kernels
// ---------------------------------------------------------------------------
__global__ __launch_bounds__(256)
void round_kernel(const float* __restrict__ src, __half* __restrict__ dst, int n)
{
    int i = blockIdx.x * 256 + threadIdx.x;
    if (i < n) dst[i] = __float2half_rn(src[i]);
}

// W[K,Nc] -> W^T[Nc,K] single fp16
__global__ __launch_bounds__(256)
void tsingle_kernel(const float* __restrict__ W, __half* __restrict__ T,
                    int K, int Nc)
{
    __shared__ float t[32][33];
    const int n0 = blockIdx.x * 32;
    const int k0 = blockIdx.y * 32;
    const int lx = threadIdx.x & 31;
    const int ly = threadIdx.x >> 5;
    #pragma unroll
    for (int r = ly; r < 32; r += 8)
        t[r][lx] = W[(long)(k0 + r) * Nc + n0 + lx];
    __syncthreads();
    #pragma unroll
    for (int r = ly; r < 32; r += 8)
        T[(long)(n0 + r) * K + k0 + lx] = __float2half_rn(t[lx][r]);
}

// ---------------------------------------------------------------------------
// fp16 flash attention. CTA = 128 queries of one (b,h) slice. 8 warps.
// S = Q K^T (single pass, Q pre-scaled by ATT_SCALE*log2e, exp2 softmax).
// O += P V (single pass). Keys 64/tile, 16 tiles, double-buffered.
// Epilogue writes fp16 context only (no residual — see R13 error ledger).
// ---------------------------------------------------------------------------
#define AT_STRIDE 112                       // bytes per smem row (48 fp16 + pad)
#define AT_Q_BYTES (128 * AT_STRIDE)        // 14336
#define AT_T_BYTES (64 * AT_STRIDE)         // 7168
#define AT_STAGE (2 * AT_T_BYTES)           // 14336 (K, V)
#define ATT_SMEM (AT_Q_BYTES + 2 * AT_STAGE)   // 43008

__device__ __forceinline__ void at_stage(
    uint32_t sdst, const __half* kh, const __half* vh, int key0, int tid)
{
    for (int i = tid; i < 384; i += 256) {
        const int r = i / 6, c = i % 6;
        const uint32_t off = r * AT_STRIDE + c * 16;
        const long gm = (long)(key0 + r) * DH + c * 8;
        CP_ASYNC16(sdst + off,              kh + gm);
        CP_ASYNC16(sdst + AT_T_BYTES + off, vh + gm);
    }
}

__global__ __launch_bounds__(256)
void attn_mma(const __half* __restrict__ qkvhi, __half* __restrict__ Ch)
{
    extern __shared__ char smem[];
    const uint32_t sb = smem_u32(smem);
    const int tid = threadIdx.x;
    const int wid = tid >> 5;
    const int lane = tid & 31;
    const int slice = blockIdx.y;
    const int q0 = blockIdx.x << 7;

    const long base = (long)(slice >> 4) * HEAD_BLK + (long)(slice & 15) * SLICE_SZ;
    const __half* qh = qkvhi + base + (long)q0 * DH;
    const __half* kh = qkvhi + THIRD + base;
    const __half* vh = qkvhi + 2L * THIRD + base;

    // group 0: Q tile
    for (int i = tid; i < 768; i += 256) {
        const int r = i / 6, c = i % 6;
        CP_ASYNC16(sb + r * AT_STRIDE + c * 16, qh + (long)r * DH + c * 8);
    }
    CP_COMMIT();
    // group 1: KV stage 0
    at_stage(sb + AT_Q_BYTES, kh, vh, 0, tid);
    CP_COMMIT();
    CP_WAIT1();          // Q retired (this thread)
    __syncthreads();     // Q visible to all

    // Q fragments (kept in regs, pre-scaled by ATT_SCALE*log2e)
    uint32_t qhf[3][4];
    {
        const int aRow = wid * 16 + ((lane >> 3) & 1) * 8 + (lane & 7);
        const int aColB = (lane >> 4) * 16;
        const __half2 qs = __float2half2_rn(QSCALE);
        #pragma unroll
        for (int ks = 0; ks < 3; ++ks) {
            uint32_t addr = sb + aRow * AT_STRIDE + aColB + ks * 32;
            LDSM_X4(qhf[ks][0], qhf[ks][1], qhf[ks][2], qhf[ks][3], addr);
            #pragma unroll
            for (int r = 0; r < 4; ++r) {
                __half2 v = *(__half2*)&qhf[ks][r];
                v = __hmul2(v, qs);
                qhf[ks][r] = *(uint32_t*)&v;
            }
        }
    }

    float m1 = -INFINITY, m2 = -INFINITY, l1 = 0.f, l2 = 0.f;
    float o[6][4];
    #pragma unroll
    for (int n = 0; n < 6; ++n)
        #pragma unroll
        for (int r = 0; r < 4; ++r) o[n][r] = 0.f;

    const int kpair = lane >> 3;
    const int kRowOff = (kpair >> 1) * 8 + (lane & 7);
    const int kColB = (kpair & 1) * 16;
    const int vRowOff = (lane & 7) + ((lane >> 3) & 1) * 8;

    for (int kt = 0; kt < 16; ++kt) {
        CP_WAIT0();        // stage kt retired (this thread)
        __syncthreads();   // stage-kt visible; compute kt-1 done everywhere
        if (kt + 1 < 16) {
            at_stage(sb + AT_Q_BYTES + ((kt + 1) & 1) * AT_STAGE,
                     kh, vh, (kt + 1) * 64, tid);
            CP_COMMIT();
        }

        const uint32_t stg = sb + AT_Q_BYTES + (kt & 1) * AT_STAGE;

        // ---- S = Q K^T (pre-scaled; log2 domain) ----
        float s[8][4];
        #pragma unroll
        for (int j = 0; j < 8; ++j)
            #pragma unroll
            for (int r = 0; r < 4; ++r) s[j][r] = 0.f;

        #pragma unroll
        for (int g = 0; g < 4; ++g) {
            #pragma unroll
            for (int ks = 0; ks < 3; ++ks) {
                const uint32_t ka = stg + (g * 16 + kRowOff) * AT_STRIDE
                                    + kColB + ks * 32;
                uint32_t kb[4];
                LDSM_X4(kb[0], kb[1], kb[2], kb[3], ka);
                MMA_F16(s[2 * g],     qhf[ks], kb);
                MMA_F16(s[2 * g + 1], qhf[ks], kb + 2);
            }
        }

        // ---- online softmax (exp2 domain) ----
        float mx1 = s[0][0], mx2 = s[0][2];
        #pragma unroll
        for (int j = 0; j < 8; ++j) {
            mx1 = fmaxf(mx1, fmaxf(s[j][0], s[j][1]));
            mx2 = fmaxf(mx2, fmaxf(s[j][2], s[j][3]));
        }
        mx1 = fmaxf(mx1, __shfl_xor_sync(0xffffffffu, mx1, 1));
        mx1 = fmaxf(mx1, __shfl_xor_sync(0xffffffffu, mx1, 2));
        mx2 = fmaxf(mx2, __shfl_xor_sync(0xffffffffu, mx2, 1));
        mx2 = fmaxf(mx2, __shfl_xor_sync(0xffffffffu, mx2, 2));

        const float nm1 = fmaxf(m1, mx1);
        const float nm2 = fmaxf(m2, mx2);
        const float e1 = ex2f(m1 - nm1);
        const float e2 = ex2f(m2 - nm2);
        m1 = nm1; m2 = nm2;

        float sum1 = 0.f, sum2 = 0.f;
        #pragma unroll
        for (int j = 0; j < 8; ++j) {
            s[j][0] = ex2f(s[j][0] - m1);
            s[j][1] = ex2f(s[j][1] - m1);
            s[j][2] = ex2f(s[j][2] - m2);
            s[j][3] = ex2f(s[j][3] - m2);
            sum1 += s[j][0] + s[j][1];
            sum2 += s[j][2] + s[j][3];
        }
        sum1 += __shfl_xor_sync(0xffffffffu, sum1, 1);
        sum1 += __shfl_xor_sync(0xffffffffu, sum1, 2);
        sum2 += __shfl_xor_sync(0xffffffffu, sum2, 1);
        sum2 += __shfl_xor_sync(0xffffffffu, sum2, 2);
        l1 = l1 * e1 + sum1;
        l2 = l2 * e2 + sum2;

        #pragma unroll
        for (int n = 0; n < 6; ++n) {
            o[n][0] *= e1; o[n][1] *= e1;
            o[n][2] *= e2; o[n][3] *= e2;
        }

        // ---- O += P V (single pass) ----
        #pragma unroll
        for (int kk = 0; kk < 4; ++kk) {
            uint32_t ph[4];
            ph[0] = packh2(s[2 * kk][0],     s[2 * kk][1]);
            ph[1] = packh2(s[2 * kk][2],     s[2 * kk][3]);
            ph[2] = packh2(s[2 * kk + 1][0], s[2 * kk + 1][1]);
            ph[3] = packh2(s[2 * kk + 1][2], s[2 * kk + 1][3]);

            const uint32_t vrowA = stg + AT_T_BYTES
                                   + (kk * 16 + vRowOff) * AT_STRIDE;
            #pragma unroll
            for (int n = 0; n < 6; ++n) {
                uint32_t vb[2];
                LDSM_X2T(vb[0], vb[1], vrowA + n * 16);
                MMA_F16(o[n], ph, vb);
            }
        }
    }

    // ---- epilogue: write fp16 context at raw-reshape-flat offsets ----
    const float inv1 = 1.f / l1;
    const float inv2 = 1.f / l2;
    const long r1 = q0 + wid * 16 + (lane >> 2);
    const long r2 = r1 + 8;
    #pragma unroll
    for (int n = 0; n < 6; ++n) {
        const int col = n * 8 + (lane & 3) * 2;
        *(uint32_t*)(Ch + base + r1 * DH + col) =
            packh2(o[n][0] * inv1, o[n][1] * inv1);
        *(uint32_t*)(Ch + base + r2 * DH + col) =
            packh2(o[n][2] * inv2, o[n][3] * inv2);
    }
}

// ---------------------------------------------------------------------------
extern "C" void kernel_launch(void* const* d_in, const int* in_sizes, int n_in,
                              void* d_out, int out_size)
{
    (void)in_sizes; (void)n_in; (void)out_size;
    const float* x    = (const float*)d_in[0];
    const float* Wqkv = (const float*)d_in[1];
    const float* Wo   = (const float*)d_in[2];
    const float* bo   = (const float*)d_in[3];
    float* out = (float*)d_out;

    void *qkvhi, *xh, *ch, *wqh, *woh;
    cudaGetSymbolAddress(&qkvhi, g_qkvhi);
    cudaGetSymbolAddress(&xh, g_xh);
    cudaGetSymbolAddress(&ch, g_ch);
    cudaGetSymbolAddress(&wqh, g_wqh);
    cudaGetSymbolAddress(&woh, g_woh);

    cudaFuncSetAttribute(mma_gemm, cudaFuncAttributeMaxDynamicSharedMemorySize,
                         GEMM_SMEM);
    cudaFuncSetAttribute(attn_mma, cudaFuncAttributeMaxDynamicSharedMemorySize,
                         ATT_SMEM);

    // prep: round x to fp16, transpose weights to single fp16
    round_kernel<<<(ROWS * DIMM + 255) / 256, 256>>>(
        x, (__half*)xh, ROWS * DIMM);
    tsingle_kernel<<<dim3(QKVC / 32, DIMM / 32), 256>>>(
        Wqkv, (__half*)wqh, DIMM, QKVC);
    tsingle_kernel<<<dim3(DIMM / 32, DIMM / 32), 256>>>(
        Wo, (__half*)woh, DIMM, DIMM);

    // 1) QKV projection (single-pass fp16) -> fp16 qkv
    mma_gemm<<<dim3(QKVC / 128, ROWS / 128), 256, GEMM_SMEM>>>(
        (const __half*)xh, nullptr, (const __half*)wqh,
        nullptr, nullptr, (__half*)qkvhi,
        ROWS, QKVC, DIMM);

    // 2) fp16 flash attention -> fp16 context
    attn_mma<<<dim3(NSEQ / 128, NB * HEADS), 256, ATT_SMEM>>>(
        (const __half*)qkvhi, (__half*)ch);

    // 3) output projection (single-pass fp16, +bias) -> fp32 out
    mma_gemm<<<dim3(DIMM / 128, ROWS / 128), 256, GEMM_SMEM>>>(
        (const __half*)ch, nullptr, (const __half*)woh,
        bo, out, nullptr,
        ROWS, DIMM, DIMM);
}

// round 15
// speedup vs baseline: 1.6837x; 1.0165x over previous
#include <cuda_runtime.h>
#include <cuda_fp16.h>
#include <math.h>
#include <stdint.h>

#define DIMM 768
#define HEADS 16
#define DH 48
#define NB 8
#define NSEQ 1024
#define ROWS 8192            // NB*NSEQ
#define QKVC 2304            // 3*DIMM
#define SLICE_SZ 49152       // NSEQ*DH
#define HEAD_BLK 786432      // HEADS*NSEQ*DH
#define THIRD 6291456        // NB*HEAD_BLK
// Q pre-scale: ATT_SCALE * log2(e) folded into Q fragments; softmax uses ex2.
#define QSCALE 0.20823030778170076f

// ---------------- scratch (__device__ globals; no allocation allowed) ------
__device__ __half g_qkvhi[ROWS * QKVC];      // qkv fp16 (GEMM1 out)
__device__ __half g_xh[ROWS * DIMM];         // x fp16 (single precision)
__device__ __half g_ch[ROWS * DIMM];         // context fp16 (attn out)
__device__ __half g_wqh[QKVC * DIMM];        // Wqkv^T fp16 [2304,768]
__device__ __half g_woh[DIMM * DIMM];        // Wo^T fp16   [768,768]

// ---------------- PTX helpers (arch-agnostic: sm_80+ features only) --------
__device__ __forceinline__ uint32_t smem_u32(const void* p) {
    uint32_t a;
    asm("{ .reg .u64 t; cvta.to.shared.u64 t, %1; cvt.u32.u64 %0, t; }"
        : "=r"(a) : "l"(p));
    return a;
}
__device__ __forceinline__ float ex2f(float x) {
    float r;
    asm("ex2.approx.ftz.f32 %0, %1;" : "=f"(r) : "f"(x));
    return r;
}
#define LDSM_X4(r0, r1, r2, r3, addr) \
    asm volatile("ldmatrix.sync.aligned.m8n8.x4.shared.b16 {%0,%1,%2,%3}, [%4];" \
                 : "=r"(r0), "=r"(r1), "=r"(r2), "=r"(r3) : "r"(addr))
#define LDSM_X2(r0, r1, addr) \
    asm volatile("ldmatrix.sync.aligned.m8n8.x2.shared.b16 {%0,%1}, [%2];" \
                 : "=r"(r0), "=r"(r1) : "r"(addr))
#define LDSM_X2T(r0, r1, addr) \
    asm volatile("ldmatrix.sync.aligned.m8n8.x2.trans.shared.b16 {%0,%1}, [%2];" \
                 : "=r"(r0), "=r"(r1) : "r"(addr))
#define MMA_F16(c, a, b) \
    asm volatile("mma.sync.aligned.m16n8k16.row.col.f32.f16.f16.f32 " \
                 "{%0,%1,%2,%3},{%4,%5,%6,%7},{%8,%9},{%0,%1,%2,%3};" \
                 : "+f"((c)[0]), "+f"((c)[1]), "+f"((c)[2]), "+f"((c)[3]) \
                 : "r"((a)[0]), "r"((a)[1]), "r"((a)[2]), "r"((a)[3]), \
                   "r"((b)[0]), "r"((b)[1]))
#define CP_ASYNC16(s, g) \
    asm volatile("cp.async.cg.shared.global [%0], [%1], 16;" :: "r"(s), "l"(g))
#define CP_COMMIT() asm volatile("cp.async.commit_group;" ::: "memory")
#define CP_WAIT1()  asm volatile("cp.async.wait_group 1;" ::: "memory")
#define CP_WAIT0()  asm volatile("cp.async.wait_group 0;" ::: "memory")

__device__ __forceinline__ uint32_t packh2(float a, float b) {
    __half2 t;
    t.x = __float2half_rn(a);
    t.y = __float2half_rn(b);
    return *(uint32_t*)&t;
}

// ---------------------------------------------------------------------------
// fp16 GEMM on mma.sync: C = A @ B^T (+bias). BM=BN=128, BK=32, 8 warps,
// 2 tiles/stage (A, B), 3-stage pipeline. Single-pass fp16 operands.
// ---------------------------------------------------------------------------
#define BK 32
#define ROW_BYTES 80
#define TILE_BYTES (128 * ROW_BYTES)       // 10240
#define STAGE_BYTES (3 * TILE_BYTES)       // 30720 (A, [unused], B) layout kept
#define NSTAGE 3
#define GEMM_SMEM (NSTAGE * STAGE_BYTES)   // 92160

__device__ __forceinline__ void stage_load(
    uint32_t sbyte, const __half* s0, const __half* s2,
    int K, long kOff, int tid)
{
    #pragma unroll
    for (int m = 0; m < 2; ++m) {
        const __half* src = (m == 0) ? s0 : s2;
        const uint32_t mo = (m == 0) ? 0u : 2u * TILE_BYTES;
        #pragma unroll
        for (int t = 0; t < 2; ++t) {
            const int ch = tid * 2 + t;          // 0..511
            const int row = ch >> 2;
            const int cc = ch & 3;
            const void* g = src + (long)row * K + kOff + cc * 8;
            uint32_t s = sbyte + mo + row * ROW_BYTES + cc * 16;
            CP_ASYNC16(s, g);
        }
    }
}

__global__ __launch_bounds__(256, 2)
void mma_gemm(const __half* __restrict__ A, const __half* __restrict__ B,
              const float* __restrict__ bias, float* __restrict__ C,
              __half* __restrict__ Ohi,
              int M, int Nc, int K)
{
    extern __shared__ char smem[];
    const uint32_t sb = smem_u32(smem);
    const int tid = threadIdx.x;
    const int wid = tid >> 5;
    const int lane = tid & 31;
    const int wr = wid >> 2;
    const int wc = wid & 3;
    const int rowBase = blockIdx.y << 7;
    const int colBase = blockIdx.x << 7;
    const int nch = K / BK;

    const __half* pA = A + (long)rowBase * K;
    const __half* pB = B + (long)colBase * K;

    const int r8 = lane & 7;
    const int quad = lane >> 3;
    const int aRow = wr * 64 + (quad & 1) * 8 + r8;
    const int aColB = ((quad >> 1) * 8) * 2;
    const int bRow = wc * 32 + (lane & 7);
    const int bColB = (((lane >> 3) & 1) * 8) * 2;

    float acc[4][4][4];
    #pragma unroll
    for (int i = 0; i < 4; ++i)
        #pragma unroll
        for (int j = 0; j < 4; ++j)
            #pragma unroll
            for (int r = 0; r < 4; ++r) acc[i][j][r] = 0.f;

    // prologue: stages 0, 1 in flight
    stage_load(sb, pA, pB, K, 0, tid);
    CP_COMMIT();
    stage_load(sb + STAGE_BYTES, pA, pB, K, BK, tid);
    CP_COMMIT();

    for (int c = 0; c < nch; ++c) {
        if (c + 1 < nch) { CP_WAIT1(); } else { CP_WAIT0(); }  // stage c retired
        __syncthreads();   // stage-c visible to all; compute c-1 done everywhere
        if (c + 2 < nch) { // slot (c+2)%NSTAGE freed (last read at compute c-1)
            stage_load(sb + ((c + 2) % NSTAGE) * STAGE_BYTES, pA, pB,
                       K, (long)(c + 2) * BK, tid);
            CP_COMMIT();
        }

        const uint32_t stg = sb + (c % NSTAGE) * STAGE_BYTES;
        #pragma unroll
        for (int ks = 0; ks < 2; ++ks) {
            uint32_t ah[4][4];
            #pragma unroll
            for (int i = 0; i < 4; ++i) {
                uint32_t aoff = stg + (aRow + i * 16) * ROW_BYTES + aColB + ks * 32;
                LDSM_X4(ah[i][0], ah[i][1], ah[i][2], ah[i][3], aoff);
            }
            uint32_t bfr[4][2];
            #pragma unroll
            for (int j = 0; j < 4; ++j) {
                uint32_t boff = stg + 2 * TILE_BYTES + (bRow + j * 8) * ROW_BYTES
                                + bColB + ks * 32;
                LDSM_X2(bfr[j][0], bfr[j][1], boff);
            }
            #pragma unroll
            for (int i = 0; i < 4; ++i)
                #pragma unroll
                for (int j = 0; j < 4; ++j)
                    MMA_F16(acc[i][j], ah[i], bfr[j]);
        }
    }

    #pragma unroll
    for (int i = 0; i < 4; ++i) {
        const long r0 = rowBase + wr * 64 + i * 16 + (lane >> 2);
        #pragma unroll
        for (int j = 0; j < 4; ++j) {
            const int col = wc * 32 + j * 8 + (lane & 3) * 2;
            if (Ohi != nullptr) {
                *(uint32_t*)(Ohi + r0 * Nc + colBase + col) =
                    packh2(acc[i][j][0], acc[i][j][1]);
                *(uint32_t*)(Ohi + (r0 + 8) * Nc + colBase + col) =
                    packh2(acc[i][j][2], acc[i][j][3]);
            } else {
                float b0 = 0.f, b1 = 0.f;
                if (bias != nullptr) {
                    b0 = bias[colBase + col];
                    b1 = bias[colBase + col + 1];
                }
                *(float2*)(C + r0 * Nc + colBase + col) =
                    make_float2(acc[i][j][0] + b0, acc[i][j][1] + b1);
                *(float2*)(C + (r0 + 8) * Nc + colBase + col) =
                    make_float2(acc[i][j][2] + b0, acc[i][j][3] + b1);
            }
        }
    }
}

// ---------------------------------------------------------------------------
// fused prep: round x to fp16 + transpose/round both weight matrices.
// Grid range-partitioned: [0, RB) round x; [RB, RB+WQB) Wqkv^T; rest Wo^T.
// ---------------------------------------------------------------------------
#define RB ((ROWS * DIMM) / 256)           // 24576
#define WQB ((QKVC / 32) * (DIMM / 32))    // 1728

__device__ __forceinline__ void tpose_tile(
    const float* __restrict__ W, __half* __restrict__ T,
    int K, int Nc, int n0, int k0, float t[32][33])
{
    const int lx = threadIdx.x & 31;
    const int ly = threadIdx.x >> 5;
    #pragma unroll
    for (int r = ly; r < 32; r += 8)
        t[r][lx] = W[(long)(k0 + r) * Nc + n0 + lx];
    __syncthreads();
    #pragma unroll
    for (int r = ly; r < 32; r += 8)
        T[(long)(n0 + r) * K + k0 + lx] = __float2half_rn(t[lx][r]);
}

__global__ __launch_bounds__(256)
void prep_kernel(const float* __restrict__ x, __half* __restrict__ xh,
                 const float* __restrict__ Wqkv, __half* __restrict__ wqh,
                 const float* __restrict__ Wo, __half* __restrict__ woh)
{
    __shared__ float t[32][33];
    const int b = blockIdx.x;
    if (b < RB) {
        const int i = b * 256 + threadIdx.x;   // ROWS*DIMM is a multiple of 256
        xh[i] = __float2half_rn(x[i]);
    } else if (b < RB + WQB) {
        const int bb = b - RB;
        tpose_tile(Wqkv, wqh, DIMM, QKVC,
                   (bb % (QKVC / 32)) * 32, (bb / (QKVC / 32)) * 32, t);
    } else {
        const int bb = b - RB - WQB;
        tpose_tile(Wo, woh, DIMM, DIMM,
                   (bb % (DIMM / 32)) * 32, (bb / (DIMM / 32)) * 32, t);
    }
}

// ---------------------------------------------------------------------------
// fp16 flash attention. CTA = 128 queries of one (b,h) slice. 8 warps.
// 128-key stages (2 x 64-key sub-tiles per barrier -> 8 barriers not 16);
// compute sub-tile stays 64 keys so register footprint is unchanged.
// S = Q K^T (Q pre-scaled by ATT_SCALE*log2e, exp2 softmax); O += P V.
// ---------------------------------------------------------------------------
#define AT_STRIDE 112                       // bytes per smem row (48 fp16 + pad)
#define AT_Q_BYTES (128 * AT_STRIDE)        // 14336
#define AT_T_BYTES (64 * AT_STRIDE)         // 7168
#define AT_SUB (2 * AT_T_BYTES)             // 14336 (K, V for 64 keys)
#define AT_STAGE128 (2 * AT_SUB)            // 28672 (128 keys)
#define ATT_SMEM (AT_Q_BYTES + 2 * AT_STAGE128)   // 71680

__device__ __forceinline__ void at_stage64(
    uint32_t sdst, const __half* kh, const __half* vh, int key0, int tid)
{
    for (int i = tid; i < 384; i += 256) {
        const int r = i / 6, c = i % 6;
        const uint32_t off = r * AT_STRIDE + c * 16;
        const long gm = (long)(key0 + r) * DH + c * 8;
        CP_ASYNC16(sdst + off,              kh + gm);
        CP_ASYNC16(sdst + AT_T_BYTES + off, vh + gm);
    }
}

__global__ __launch_bounds__(256)
void attn_mma(const __half* __restrict__ qkvhi, __half* __restrict__ Ch)
{
    extern __shared__ char smem[];
    const uint32_t sb = smem_u32(smem);
    const int tid = threadIdx.x;
    const int wid = tid >> 5;
    const int lane = tid & 31;
    const int slice = blockIdx.y;
    const int q0 = blockIdx.x << 7;

    const long base = (long)(slice >> 4) * HEAD_BLK + (long)(slice & 15) * SLICE_SZ;
    const __half* qh = qkvhi + base + (long)q0 * DH;
    const __half* kh = qkvhi + THIRD + base;
    const __half* vh = qkvhi + 2L * THIRD + base;

    // group 0: Q tile
    for (int i = tid; i < 768; i += 256) {
        const int r = i / 6, c = i % 6;
        CP_ASYNC16(sb + r * AT_STRIDE + c * 16, qh + (long)r * DH + c * 8);
    }
    CP_COMMIT();
    // group 1: 128-key stage 0
    at_stage64(sb + AT_Q_BYTES,          kh, vh, 0,  tid);
    at_stage64(sb + AT_Q_BYTES + AT_SUB, kh, vh, 64, tid);
    CP_COMMIT();
    CP_WAIT1();          // Q retired (this thread)
    __syncthreads();     // Q visible to all

    // Q fragments (kept in regs, pre-scaled by ATT_SCALE*log2e)
    uint32_t qhf[3][4];
    {
        const int aRow = wid * 16 + ((lane >> 3) & 1) * 8 + (lane & 7);
        const int aColB = (lane >> 4) * 16;
        const __half2 qs = __float2half2_rn(QSCALE);
        #pragma unroll
        for (int ks = 0; ks < 3; ++ks) {
            uint32_t addr = sb + aRow * AT_STRIDE + aColB + ks * 32;
            LDSM_X4(qhf[ks][0], qhf[ks][1], qhf[ks][2], qhf[ks][3], addr);
            #pragma unroll
            for (int r = 0; r < 4; ++r) {
                __half2 v = *(__half2*)&qhf[ks][r];
                v = __hmul2(v, qs);
                qhf[ks][r] = *(uint32_t*)&v;
            }
        }
    }

    float m1 = -INFINITY, m2 = -INFINITY, l1 = 0.f, l2 = 0.f;
    float o[6][4];
    #pragma unroll
    for (int n = 0; n < 6; ++n)
        #pragma unroll
        for (int r = 0; r < 4; ++r) o[n][r] = 0.f;

    const int kpair = lane >> 3;
    const int kRowOff = (kpair >> 1) * 8 + (lane & 7);
    const int kColB = (kpair & 1) * 16;
    const int vRowOff = (lane & 7) + ((lane >> 3) & 1) * 8;

    for (int kt = 0; kt < 8; ++kt) {
        CP_WAIT0();        // stage kt (128 keys) retired for this thread
        __syncthreads();   // stage-kt visible; compute kt-1 done everywhere
        if (kt + 1 < 8) {
            const uint32_t dst = sb + AT_Q_BYTES + ((kt + 1) & 1) * AT_STAGE128;
            at_stage64(dst,          kh, vh, (kt + 1) * 128,      tid);
            at_stage64(dst + AT_SUB, kh, vh, (kt + 1) * 128 + 64, tid);
            CP_COMMIT();
        }

        #pragma unroll
        for (int sub = 0; sub < 2; ++sub) {
            const uint32_t stg = sb + AT_Q_BYTES + (kt & 1) * AT_STAGE128
                                 + sub * AT_SUB;

            // ---- S = Q K^T (pre-scaled; log2 domain) ----
            float s[8][4];
            #pragma unroll
            for (int j = 0; j < 8; ++j)
                #pragma unroll
                for (int r = 0; r < 4; ++r) s[j][r] = 0.f;

            #pragma unroll
            for (int g = 0; g < 4; ++g) {
                #pragma unroll
                for (int ks = 0; ks < 3; ++ks) {
                    const uint32_t ka = stg + (g * 16 + kRowOff) * AT_STRIDE
                                        + kColB + ks * 32;
                    uint32_t kb[4];
                    LDSM_X4(kb[0], kb[1], kb[2], kb[3], ka);
                    MMA_F16(s[2 * g],     qhf[ks], kb);
                    MMA_F16(s[2 * g + 1], qhf[ks], kb + 2);
                }
            }

            // ---- online softmax (exp2 domain) ----
            float mx1 = s[0][0], mx2 = s[0][2];
            #pragma unroll
            for (int j = 0; j < 8; ++j) {
                mx1 = fmaxf(mx1, fmaxf(s[j][0], s[j][1]));
                mx2 = fmaxf(mx2, fmaxf(s[j][2], s[j][3]));
            }
            mx1 = fmaxf(mx1, __shfl_xor_sync(0xffffffffu, mx1, 1));
            mx1 = fmaxf(mx1, __shfl_xor_sync(0xffffffffu, mx1, 2));
            mx2 = fmaxf(mx2, __shfl_xor_sync(0xffffffffu, mx2, 1));
            mx2 = fmaxf(mx2, __shfl_xor_sync(0xffffffffu, mx2, 2));

            const float nm1 = fmaxf(m1, mx1);
            const float nm2 = fmaxf(m2, mx2);
            const float e1 = ex2f(m1 - nm1);
            const float e2 = ex2f(m2 - nm2);
            m1 = nm1; m2 = nm2;

            float sum1 = 0.f, sum2 = 0.f;
            #pragma unroll
            for (int j = 0; j < 8; ++j) {
                s[j][0] = ex2f(s[j][0] - m1);
                s[j][1] = ex2f(s[j][1] - m1);
                s[j][2] = ex2f(s[j][2] - m2);
                s[j][3] = ex2f(s[j][3] - m2);
                sum1 += s[j][0] + s[j][1];
                sum2 += s[j][2] + s[j][3];
            }
            sum1 += __shfl_xor_sync(0xffffffffu, sum1, 1);
            sum1 += __shfl_xor_sync(0xffffffffu, sum1, 2);
            sum2 += __shfl_xor_sync(0xffffffffu, sum2, 1);
            sum2 += __shfl_xor_sync(0xffffffffu, sum2, 2);
            l1 = l1 * e1 + sum1;
            l2 = l2 * e2 + sum2;

            #pragma unroll
            for (int n = 0; n < 6; ++n) {
                o[n][0] *= e1; o[n][1] *= e1;
                o[n][2] *= e2; o[n][3] *= e2;
            }

            // ---- O += P V (single pass) ----
            #pragma unroll
            for (int kk = 0; kk < 4; ++kk) {
                uint32_t ph[4];
                ph[0] = packh2(s[2 * kk][0],     s[2 * kk][1]);
                ph[1] = packh2(s[2 * kk][2],     s[2 * kk][3]);
                ph[2] = packh2(s[2 * kk + 1][0], s[2 * kk + 1][1]);
                ph[3] = packh2(s[2 * kk + 1][2], s[2 * kk + 1][3]);

                const uint32_t vrowA = stg + AT_T_BYTES
                                       + (kk * 16 + vRowOff) * AT_STRIDE;
                #pragma unroll
                for (int n = 0; n < 6; ++n) {
                    uint32_t vb[2];
                    LDSM_X2T(vb[0], vb[1], vrowA + n * 16);
                    MMA_F16(o[n], ph, vb);
                }
            }
        }
    }

    // ---- epilogue: write fp16 context at raw-reshape-flat offsets ----
    const float inv1 = 1.f / l1;
    const float inv2 = 1.f / l2;
    const long r1 = q0 + wid * 16 + (lane >> 2);
    const long r2 = r1 + 8;
    #pragma unroll
    for (int n = 0; n < 6; ++n) {
        const int col = n * 8 + (lane & 3) * 2;
        *(uint32_t*)(Ch + base + r1 * DH + col) =
            packh2(o[n][0] * inv1, o[n][1] * inv1);
        *(uint32_t*)(Ch + base + r2 * DH + col) =
            packh2(o[n][2] * inv2, o[n][3] * inv2);
    }
}

// ---------------------------------------------------------------------------
extern "C" void kernel_launch(void* const* d_in, const int* in_sizes, int n_in,
                              void* d_out, int out_size)
{
    (void)in_sizes; (void)n_in; (void)out_size;
    const float* x    = (const float*)d_in[0];
    const float* Wqkv = (const float*)d_in[1];
    const float* Wo   = (const float*)d_in[2];
    const float* bo   = (const float*)d_in[3];
    float* out = (float*)d_out;

    void *qkvhi, *xh, *ch, *wqh, *woh;
    cudaGetSymbolAddress(&qkvhi, g_qkvhi);
    cudaGetSymbolAddress(&xh, g_xh);
    cudaGetSymbolAddress(&ch, g_ch);
    cudaGetSymbolAddress(&wqh, g_wqh);
    cudaGetSymbolAddress(&woh, g_woh);

    cudaFuncSetAttribute(mma_gemm, cudaFuncAttributeMaxDynamicSharedMemorySize,
                         GEMM_SMEM);
    cudaFuncSetAttribute(attn_mma, cudaFuncAttributeMaxDynamicSharedMemorySize,
                         ATT_SMEM);

    // 0) fused prep: round x, transpose+round Wqkv and Wo
    const int WOB = (DIMM / 32) * (DIMM / 32);   // 576
    prep_kernel<<<RB + WQB + WOB, 256>>>(
        x, (__half*)xh, Wqkv, (__half*)wqh, Wo, (__half*)woh);

    // 1) QKV projection (single-pass fp16) -> fp16 qkv
    mma_gemm<<<dim3(QKVC / 128, ROWS / 128), 256, GEMM_SMEM>>>(
        (const __half*)xh, (const __half*)wqh,
        nullptr, nullptr, (__half*)qkvhi,
        ROWS, QKVC, DIMM);

    // 2) fp16 flash attention -> fp16 context
    attn_mma<<<dim3(NSEQ / 128, NB * HEADS), 256, ATT_SMEM>>>(
        (const __half*)qkvhi, (__half*)ch);

    // 3) output projection (single-pass fp16, +bias) -> fp32 out
    mma_gemm<<<dim3(DIMM / 128, ROWS / 128), 256, GEMM_SMEM>>>(
        (const __half*)ch, (const __half*)woh,
        bo, out, nullptr,
        ROWS, DIMM, DIMM);
}

// round 16
// speedup vs baseline: 1.7305x; 1.0278x over previous
#include <cuda_runtime.h>
#include <cuda_fp16.h>
#include <math.h>
#include <stdint.h>

#define DIMM 768
#define HEADS 16
#define DH 48
#define NB 8
#define NSEQ 1024
#define ROWS 8192            // NB*NSEQ
#define QKVC 2304            // 3*DIMM
#define SLICE_SZ 49152       // NSEQ*DH
#define HEAD_BLK 786432      // HEADS*NSEQ*DH
#define THIRD 6291456        // NB*HEAD_BLK
// Q pre-scale: ATT_SCALE * log2(e) folded into Q fragments; softmax uses ex2.
#define QSCALE 0.20823030778170076f

// ---------------- scratch (__device__ globals; no allocation allowed) ------
__device__ __half g_qkvhi[ROWS * QKVC];      // qkv fp16 (GEMM1 out)
__device__ __half g_xh[ROWS * DIMM];         // x fp16 (single precision)
__device__ __half g_ch[ROWS * DIMM];         // context fp16 (attn out)
__device__ __half g_wqh[QKVC * DIMM];        // Wqkv^T fp16 [2304,768]
__device__ __half g_woh[DIMM * DIMM];        // Wo^T fp16   [768,768]

// ---------------- PTX helpers (arch-agnostic: sm_80+ features only) --------
__device__ __forceinline__ uint32_t smem_u32(const void* p) {
    uint32_t a;
    asm("{ .reg .u64 t; cvta.to.shared.u64 t, %1; cvt.u32.u64 %0, t; }"
        : "=r"(a) : "l"(p));
    return a;
}
__device__ __forceinline__ float ex2f(float x) {
    float r;
    asm("ex2.approx.ftz.f32 %0, %1;" : "=f"(r) : "f"(x));
    return r;
}
#define LDSM_X4(r0, r1, r2, r3, addr) \
    asm volatile("ldmatrix.sync.aligned.m8n8.x4.shared.b16 {%0,%1,%2,%3}, [%4];" \
                 : "=r"(r0), "=r"(r1), "=r"(r2), "=r"(r3) : "r"(addr))
#define LDSM_X2(r0, r1, addr) \
    asm volatile("ldmatrix.sync.aligned.m8n8.x2.shared.b16 {%0,%1}, [%2];" \
                 : "=r"(r0), "=r"(r1) : "r"(addr))
#define LDSM_X2T(r0, r1, addr) \
    asm volatile("ldmatrix.sync.aligned.m8n8.x2.trans.shared.b16 {%0,%1}, [%2];" \
                 : "=r"(r0), "=r"(r1) : "r"(addr))
#define MMA_F16(c, a, b) \
    asm volatile("mma.sync.aligned.m16n8k16.row.col.f32.f16.f16.f32 " \
                 "{%0,%1,%2,%3},{%4,%5,%6,%7},{%8,%9},{%0,%1,%2,%3};" \
                 : "+f"((c)[0]), "+f"((c)[1]), "+f"((c)[2]), "+f"((c)[3]) \
                 : "r"((a)[0]), "r"((a)[1]), "r"((a)[2]), "r"((a)[3]), \
                   "r"((b)[0]), "r"((b)[1]))
#define CP_ASYNC16(s, g) \
    asm volatile("cp.async.cg.shared.global [%0], [%1], 16;" :: "r"(s), "l"(g))
#define CP_COMMIT() asm volatile("cp.async.commit_group;" ::: "memory")
#define CP_WAIT1()  asm volatile("cp.async.wait_group 1;" ::: "memory")
#define CP_WAIT0()  asm volatile("cp.async.wait_group 0;" ::: "memory")

__device__ __forceinline__ uint32_t packh2(float a, float b) {
    __half2 t;
    t.x = __float2half_rn(a);
    t.y = __float2half_rn(b);
    return *(uint32_t*)&t;
}

// ---------------------------------------------------------------------------
// fp16 GEMM on mma.sync: C = A @ B^T (+bias). BM=BN=128, BK=32, 8 warps,
// 2 tiles/stage (A, B), 3-stage pipeline. B fragments fetched with ldmatrix.x4
// covering BOTH k-slices per instruction (12 LDSM : 32 MMA per chunk).
// ---------------------------------------------------------------------------
#define BK 32
#define ROW_BYTES 80
#define TILE_BYTES (128 * ROW_BYTES)       // 10240
#define STAGE_BYTES (3 * TILE_BYTES)       // 30720 (A, [unused], B) layout kept
#define NSTAGE 3
#define GEMM_SMEM (NSTAGE * STAGE_BYTES)   // 92160

__device__ __forceinline__ void stage_load(
    uint32_t sbyte, const __half* s0, const __half* s2,
    int K, long kOff, int tid)
{
    #pragma unroll
    for (int m = 0; m < 2; ++m) {
        const __half* src = (m == 0) ? s0 : s2;
        const uint32_t mo = (m == 0) ? 0u : 2u * TILE_BYTES;
        #pragma unroll
        for (int t = 0; t < 2; ++t) {
            const int ch = tid * 2 + t;          // 0..511
            const int row = ch >> 2;
            const int cc = ch & 3;
            const void* g = src + (long)row * K + kOff + cc * 8;
            uint32_t s = sbyte + mo + row * ROW_BYTES + cc * 16;
            CP_ASYNC16(s, g);
        }
    }
}

__global__ __launch_bounds__(256, 2)
void mma_gemm(const __half* __restrict__ A, const __half* __restrict__ B,
              const float* __restrict__ bias, float* __restrict__ C,
              __half* __restrict__ Ohi,
              int M, int Nc, int K)
{
    extern __shared__ char smem[];
    const uint32_t sb = smem_u32(smem);
    const int tid = threadIdx.x;
    const int wid = tid >> 5;
    const int lane = tid & 31;
    const int wr = wid >> 2;
    const int wc = wid & 3;
    const int rowBase = blockIdx.y << 7;
    const int colBase = blockIdx.x << 7;
    const int nch = K / BK;

    const __half* pA = A + (long)rowBase * K;
    const __half* pB = B + (long)colBase * K;

    const int r8 = lane & 7;
    const int quad = lane >> 3;
    const int aRow = wr * 64 + (quad & 1) * 8 + r8;
    const int aColB = ((quad >> 1) * 8) * 2;
    // B x4 addressing: lane group g=lane>>3 selects 16-byte sub-chunk g
    // (g0,g1 = ks0 k0-7/k8-15; g2,g3 = ks1) of the 64-byte BK row.
    const int bRow = wc * 32 + (lane & 7);
    const int bColB4 = (lane >> 3) * 16;

    float acc[4][4][4];
    #pragma unroll
    for (int i = 0; i < 4; ++i)
        #pragma unroll
        for (int j = 0; j < 4; ++j)
            #pragma unroll
            for (int r = 0; r < 4; ++r) acc[i][j][r] = 0.f;

    // prologue: stages 0, 1 in flight
    stage_load(sb, pA, pB, K, 0, tid);
    CP_COMMIT();
    stage_load(sb + STAGE_BYTES, pA, pB, K, BK, tid);
    CP_COMMIT();

    for (int c = 0; c < nch; ++c) {
        if (c + 1 < nch) { CP_WAIT1(); } else { CP_WAIT0(); }  // stage c retired
        __syncthreads();   // stage-c visible to all; compute c-1 done everywhere
        if (c + 2 < nch) { // slot (c+2)%NSTAGE freed (last read at compute c-1)
            stage_load(sb + ((c + 2) % NSTAGE) * STAGE_BYTES, pA, pB,
                       K, (long)(c + 2) * BK, tid);
            CP_COMMIT();
        }

        const uint32_t stg = sb + (c % NSTAGE) * STAGE_BYTES;

        // B fragments for BOTH k-slices: 4 x ldmatrix.x4
        uint32_t bfr[4][4];
        #pragma unroll
        for (int j = 0; j < 4; ++j) {
            uint32_t boff = stg + 2 * TILE_BYTES + (bRow + j * 8) * ROW_BYTES
                            + bColB4;
            LDSM_X4(bfr[j][0], bfr[j][1], bfr[j][2], bfr[j][3], boff);
        }

        #pragma unroll
        for (int ks = 0; ks < 2; ++ks) {
            uint32_t ah[4][4];
            #pragma unroll
            for (int i = 0; i < 4; ++i) {
                uint32_t aoff = stg + (aRow + i * 16) * ROW_BYTES + aColB + ks * 32;
                LDSM_X4(ah[i][0], ah[i][1], ah[i][2], ah[i][3], aoff);
            }
            #pragma unroll
            for (int i = 0; i < 4; ++i)
                #pragma unroll
                for (int j = 0; j < 4; ++j)
                    MMA_F16(acc[i][j], ah[i], bfr[j] + 2 * ks);
        }
    }

    #pragma unroll
    for (int i = 0; i < 4; ++i) {
        const long r0 = rowBase + wr * 64 + i * 16 + (lane >> 2);
        #pragma unroll
        for (int j = 0; j < 4; ++j) {
            const int col = wc * 32 + j * 8 + (lane & 3) * 2;
            if (Ohi != nullptr) {
                *(uint32_t*)(Ohi + r0 * Nc + colBase + col) =
                    packh2(acc[i][j][0], acc[i][j][1]);
                *(uint32_t*)(Ohi + (r0 + 8) * Nc + colBase + col) =
                    packh2(acc[i][j][2], acc[i][j][3]);
            } else {
                float b0 = 0.f, b1 = 0.f;
                if (bias != nullptr) {
                    b0 = bias[colBase + col];
                    b1 = bias[colBase + col + 1];
                }
                *(float2*)(C + r0 * Nc + colBase + col) =
                    make_float2(acc[i][j][0] + b0, acc[i][j][1] + b1);
                *(float2*)(C + (r0 + 8) * Nc + colBase + col) =
                    make_float2(acc[i][j][2] + b0, acc[i][j][3] + b1);
            }
        }
    }
}

// ---------------------------------------------------------------------------
// fused prep: round x to fp16 + transpose/round both weight matrices.
// Grid range-partitioned: [0, RB) round x; [RB, RB+WQB) Wqkv^T; rest Wo^T.
// ---------------------------------------------------------------------------
#define RB ((ROWS * DIMM) / 256)           // 24576
#define WQB ((QKVC / 32) * (DIMM / 32))    // 1728

__device__ __forceinline__ void tpose_tile(
    const float* __restrict__ W, __half* __restrict__ T,
    int K, int Nc, int n0, int k0, float t[32][33])
{
    const int lx = threadIdx.x & 31;
    const int ly = threadIdx.x >> 5;
    #pragma unroll
    for (int r = ly; r < 32; r += 8)
        t[r][lx] = W[(long)(k0 + r) * Nc + n0 + lx];
    __syncthreads();
    #pragma unroll
    for (int r = ly; r < 32; r += 8)
        T[(long)(n0 + r) * K + k0 + lx] = __float2half_rn(t[lx][r]);
}

__global__ __launch_bounds__(256)
void prep_kernel(const float* __restrict__ x, __half* __restrict__ xh,
                 const float* __restrict__ Wqkv, __half* __restrict__ wqh,
                 const float* __restrict__ Wo, __half* __restrict__ woh)
{
    __shared__ float t[32][33];
    const int b = blockIdx.x;
    if (b < RB) {
        const int i = b * 256 + threadIdx.x;   // ROWS*DIMM is a multiple of 256
        xh[i] = __float2half_rn(x[i]);
    } else if (b < RB + WQB) {
        const int bb = b - RB;
        tpose_tile(Wqkv, wqh, DIMM, QKVC,
                   (bb % (QKVC / 32)) * 32, (bb / (QKVC / 32)) * 32, t);
    } else {
        const int bb = b - RB - WQB;
        tpose_tile(Wo, woh, DIMM, DIMM,
                   (bb % (DIMM / 32)) * 32, (bb / (DIMM / 32)) * 32, t);
    }
}

// ---------------------------------------------------------------------------
// fp16 flash attention. CTA = 128 queries of one (b,h) slice. 8 warps.
// 128-key stages (2 x 64-key sub-tiles per barrier -> 8 barriers); compute
// sub-tile 64 keys. __launch_bounds__(256,2) caps regs at 128 so 2 CTAs/SM
// co-reside (smem 71.7KB x 2 fits 228KB).
// ---------------------------------------------------------------------------
#define AT_STRIDE 112                       // bytes per smem row (48 fp16 + pad)
#define AT_Q_BYTES (128 * AT_STRIDE)        // 14336
#define AT_T_BYTES (64 * AT_STRIDE)         // 7168
#define AT_SUB (2 * AT_T_BYTES)             // 14336 (K, V for 64 keys)
#define AT_STAGE128 (2 * AT_SUB)            // 28672 (128 keys)
#define ATT_SMEM (AT_Q_BYTES + 2 * AT_STAGE128)   // 71680

__device__ __forceinline__ void at_stage64(
    uint32_t sdst, const __half* kh, const __half* vh, int key0, int tid)
{
    for (int i = tid; i < 384; i += 256) {
        const int r = i / 6, c = i % 6;
        const uint32_t off = r * AT_STRIDE + c * 16;
        const long gm = (long)(key0 + r) * DH + c * 8;
        CP_ASYNC16(sdst + off,              kh + gm);
        CP_ASYNC16(sdst + AT_T_BYTES + off, vh + gm);
    }
}

__global__ __launch_bounds__(256, 2)
void attn_mma(const __half* __restrict__ qkvhi, __half* __restrict__ Ch)
{
    extern __shared__ char smem[];
    const uint32_t sb = smem_u32(smem);
    const int tid = threadIdx.x;
    const int wid = tid >> 5;
    const int lane = tid & 31;
    const int slice = blockIdx.y;
    const int q0 = blockIdx.x << 7;

    const long base = (long)(slice >> 4) * HEAD_BLK + (long)(slice & 15) * SLICE_SZ;
    const __half* qh = qkvhi + base + (long)q0 * DH;
    const __half* kh = qkvhi + THIRD + base;
    const __half* vh = qkvhi + 2L * THIRD + base;

    // group 0: Q tile
    for (int i = tid; i < 768; i += 256) {
        const int r = i / 6, c = i % 6;
        CP_ASYNC16(sb + r * AT_STRIDE + c * 16, qh + (long)r * DH + c * 8);
    }
    CP_COMMIT();
    // group 1: 128-key stage 0
    at_stage64(sb + AT_Q_BYTES,          kh, vh, 0,  tid);
    at_stage64(sb + AT_Q_BYTES + AT_SUB, kh, vh, 64, tid);
    CP_COMMIT();
    CP_WAIT1();          // Q retired (this thread)
    __syncthreads();     // Q visible to all

    // Q fragments (kept in regs, pre-scaled by ATT_SCALE*log2e)
    uint32_t qhf[3][4];
    {
        const int aRow = wid * 16 + ((lane >> 3) & 1) * 8 + (lane & 7);
        const int aColB = (lane >> 4) * 16;
        const __half2 qs = __float2half2_rn(QSCALE);
        #pragma unroll
        for (int ks = 0; ks < 3; ++ks) {
            uint32_t addr = sb + aRow * AT_STRIDE + aColB + ks * 32;
            LDSM_X4(qhf[ks][0], qhf[ks][1], qhf[ks][2], qhf[ks][3], addr);
            #pragma unroll
            for (int r = 0; r < 4; ++r) {
                __half2 v = *(__half2*)&qhf[ks][r];
                v = __hmul2(v, qs);
                qhf[ks][r] = *(uint32_t*)&v;
            }
        }
    }

    float m1 = -INFINITY, m2 = -INFINITY, l1 = 0.f, l2 = 0.f;
    float o[6][4];
    #pragma unroll
    for (int n = 0; n < 6; ++n)
        #pragma unroll
        for (int r = 0; r < 4; ++r) o[n][r] = 0.f;

    const int kpair = lane >> 3;
    const int kRowOff = (kpair >> 1) * 8 + (lane & 7);
    const int kColB = (kpair & 1) * 16;
    const int vRowOff = (lane & 7) + ((lane >> 3) & 1) * 8;

    for (int kt = 0; kt < 8; ++kt) {
        CP_WAIT0();        // stage kt (128 keys) retired for this thread
        __syncthreads();   // stage-kt visible; compute kt-1 done everywhere
        if (kt + 1 < 8) {
            const uint32_t dst = sb + AT_Q_BYTES + ((kt + 1) & 1) * AT_STAGE128;
            at_stage64(dst,          kh, vh, (kt + 1) * 128,      tid);
            at_stage64(dst + AT_SUB, kh, vh, (kt + 1) * 128 + 64, tid);
            CP_COMMIT();
        }

        #pragma unroll
        for (int sub = 0; sub < 2; ++sub) {
            const uint32_t stg = sb + AT_Q_BYTES + (kt & 1) * AT_STAGE128
                                 + sub * AT_SUB;

            // ---- S = Q K^T (pre-scaled; log2 domain) ----
            float s[8][4];
            #pragma unroll
            for (int j = 0; j < 8; ++j)
                #pragma unroll
                for (int r = 0; r < 4; ++r) s[j][r] = 0.f;

            #pragma unroll
            for (int g = 0; g < 4; ++g) {
                #pragma unroll
                for (int ks = 0; ks < 3; ++ks) {
                    const uint32_t ka = stg + (g * 16 + kRowOff) * AT_STRIDE
                                        + kColB + ks * 32;
                    uint32_t kb[4];
                    LDSM_X4(kb[0], kb[1], kb[2], kb[3], ka);
                    MMA_F16(s[2 * g],     qhf[ks], kb);
                    MMA_F16(s[2 * g + 1], qhf[ks], kb + 2);
                }
            }

            // ---- online softmax (exp2 domain) ----
            float mx1 = s[0][0], mx2 = s[0][2];
            #pragma unroll
            for (int j = 0; j < 8; ++j) {
                mx1 = fmaxf(mx1, fmaxf(s[j][0], s[j][1]));
                mx2 = fmaxf(mx2, fmaxf(s[j][2], s[j][3]));
            }
            mx1 = fmaxf(mx1, __shfl_xor_sync(0xffffffffu, mx1, 1));
            mx1 = fmaxf(mx1, __shfl_xor_sync(0xffffffffu, mx1, 2));
            mx2 = fmaxf(mx2, __shfl_xor_sync(0xffffffffu, mx2, 1));
            mx2 = fmaxf(mx2, __shfl_xor_sync(0xffffffffu, mx2, 2));

            const float nm1 = fmaxf(m1, mx1);
            const float nm2 = fmaxf(m2, mx2);
            const float e1 = ex2f(m1 - nm1);
            const float e2 = ex2f(m2 - nm2);
            m1 = nm1; m2 = nm2;

            float sum1 = 0.f, sum2 = 0.f;
            #pragma unroll
            for (int j = 0; j < 8; ++j) {
                s[j][0] = ex2f(s[j][0] - m1);
                s[j][1] = ex2f(s[j][1] - m1);
                s[j][2] = ex2f(s[j][2] - m2);
                s[j][3] = ex2f(s[j][3] - m2);
                sum1 += s[j][0] + s[j][1];
                sum2 += s[j][2] + s[j][3];
            }
            sum1 += __shfl_xor_sync(0xffffffffu, sum1, 1);
            sum1 += __shfl_xor_sync(0xffffffffu, sum1, 2);
            sum2 += __shfl_xor_sync(0xffffffffu, sum2, 1);
            sum2 += __shfl_xor_sync(0xffffffffu, sum2, 2);
            l1 = l1 * e1 + sum1;
            l2 = l2 * e2 + sum2;

            #pragma unroll
            for (int n = 0; n < 6; ++n) {
                o[n][0] *= e1; o[n][1] *= e1;
                o[n][2] *= e2; o[n][3] *= e2;
            }

            // ---- O += P V (single pass) ----
            #pragma unroll
            for (int kk = 0; kk < 4; ++kk) {
                uint32_t ph[4];
                ph[0] = packh2(s[2 * kk][0],     s[2 * kk][1]);
                ph[1] = packh2(s[2 * kk][2],     s[2 * kk][3]);
                ph[2] = packh2(s[2 * kk + 1][0], s[2 * kk + 1][1]);
                ph[3] = packh2(s[2 * kk + 1][2], s[2 * kk + 1][3]);

                const uint32_t vrowA = stg + AT_T_BYTES
                                       + (kk * 16 + vRowOff) * AT_STRIDE;
                #pragma unroll
                for (int n = 0; n < 6; ++n) {
                    uint32_t vb[2];
                    LDSM_X2T(vb[0], vb[1], vrowA + n * 16);
                    MMA_F16(o[n], ph, vb);
                }
            }
        }
    }

    // ---- epilogue: write fp16 context at raw-reshape-flat offsets ----
    const float inv1 = 1.f / l1;
    const float inv2 = 1.f / l2;
    const long r1 = q0 + wid * 16 + (lane >> 2);
    const long r2 = r1 + 8;
    #pragma unroll
    for (int n = 0; n < 6; ++n) {
        const int col = n * 8 + (lane & 3) * 2;
        *(uint32_t*)(Ch + base + r1 * DH + col) =
            packh2(o[n][0] * inv1, o[n][1] * inv1);
        *(uint32_t*)(Ch + base + r2 * DH + col) =
            packh2(o[n][2] * inv2, o[n][3] * inv2);
    }
}

// ---------------------------------------------------------------------------
extern "C" void kernel_launch(void* const* d_in, const int* in_sizes, int n_in,
                              void* d_out, int out_size)
{
    (void)in_sizes; (void)n_in; (void)out_size;
    const float* x    = (const float*)d_in[0];
    const float* Wqkv = (const float*)d_in[1];
    const float* Wo   = (const float*)d_in[2];
    const float* bo   = (const float*)d_in[3];
    float* out = (float*)d_out;

    void *qkvhi, *xh, *ch, *wqh, *woh;
    cudaGetSymbolAddress(&qkvhi, g_qkvhi);
    cudaGetSymbolAddress(&xh, g_xh);
    cudaGetSymbolAddress(&ch, g_ch);
    cudaGetSymbolAddress(&wqh, g_wqh);
    cudaGetSymbolAddress(&woh, g_woh);

    cudaFuncSetAttribute(mma_gemm, cudaFuncAttributeMaxDynamicSharedMemorySize,
                         GEMM_SMEM);
    cudaFuncSetAttribute(attn_mma, cudaFuncAttributeMaxDynamicSharedMemorySize,
                         ATT_SMEM);

    // 0) fused prep: round x, transpose+round Wqkv and Wo
    const int WOB = (DIMM / 32) * (DIMM / 32);   // 576
    prep_kernel<<<RB + WQB + WOB, 256>>>(
        x, (__half*)xh, Wqkv, (__half*)wqh, Wo, (__half*)woh);

    // 1) QKV projection (single-pass fp16) -> fp16 qkv
    mma_gemm<<<dim3(QKVC / 128, ROWS / 128), 256, GEMM_SMEM>>>(
        (const __half*)xh, (const __half*)wqh,
        nullptr, nullptr, (__half*)qkvhi,
        ROWS, QKVC, DIMM);

    // 2) fp16 flash attention -> fp16 context
    attn_mma<<<dim3(NSEQ / 128, NB * HEADS), 256, ATT_SMEM>>>(
        (const __half*)qkvhi, (__half*)ch);

    // 3) output projection (single-pass fp16, +bias) -> fp32 out
    mma_gemm<<<dim3(DIMM / 128, ROWS / 128), 256, GEMM_SMEM>>>(
        (const __half*)ch, (const __half*)woh,
        bo, out, nullptr,
        ROWS, DIMM, DIMM);
}